// round 1
// baseline (speedup 1.0000x reference)
#include <cuda_runtime.h>
#include <math.h>

// Problem constants
#define B_     2
#define N_     4096
#define DIM_   1024
#define H_     16
#define D_     64
#define LAT_   1024
#define CTX_   3072
#define SEG_   12
#define CHUNK_ 256
#define BH_    (B_ * H_)          // 32
#define M_     (B_ * N_)          // 8192 rows
#define SCALE_ 0.125f             // 64^-0.5
#define LN_EPS_ 1e-5f

// ---------------------------------------------------------------------------
// Scratch (static device globals: allocation-free per harness rules)
// ---------------------------------------------------------------------------
__device__ float g_qbuf [M_ * DIM_];        // x @ Wq          [B,N,DIM]
__device__ float g_kvbuf[M_ * DIM_];        // x @ Wkv         [B,N,DIM]
__device__ float g_qs   [BH_ * N_ * D_];    // rope(q)*scale   [(BH),N,D]
__device__ float g_lkv  [BH_ * N_ * D_];    // LN(rope(kv))    [(BH),N,D]
__device__ float g_attn [M_ * DIM_];        // merged attn out [B,N,DIM]

// ---------------------------------------------------------------------------
// Tiled fp32 GEMM: C[M,N] = A[M,K] @ W[K,N] (+ bias)
// 64x64 tile, BK=16, 256 threads, 4x4 per thread.
// ---------------------------------------------------------------------------
__global__ void __launch_bounds__(256) sgemm_kernel(
    const float* __restrict__ A, const float* __restrict__ W,
    const float* __restrict__ bias, float* __restrict__ C,
    int M, int N, int K)
{
    __shared__ float As[16][64];
    __shared__ float Bs[16][64];
    int tid = threadIdx.x;
    int tx = tid & 15, ty = tid >> 4;
    int row0 = blockIdx.y * 64, col0 = blockIdx.x * 64;

    float acc[4][4];
#pragma unroll
    for (int i = 0; i < 4; i++)
#pragma unroll
        for (int j = 0; j < 4; j++) acc[i][j] = 0.f;

    for (int k0 = 0; k0 < K; k0 += 16) {
#pragma unroll
        for (int t = 0; t < 4; t++) {
            int idx = tid + t * 256;                 // 0..1023
            int ra = idx >> 4, ca = idx & 15;        // A tile: 64 x 16
            As[ca][ra] = A[(size_t)(row0 + ra) * K + k0 + ca];
            int rb = idx >> 6, cb = idx & 63;        // W tile: 16 x 64
            Bs[rb][cb] = W[(size_t)(k0 + rb) * N + col0 + cb];
        }
        __syncthreads();
#pragma unroll
        for (int kk = 0; kk < 16; kk++) {
            float a[4], b[4];
#pragma unroll
            for (int i = 0; i < 4; i++) a[i] = As[kk][ty * 4 + i];
#pragma unroll
            for (int j = 0; j < 4; j++) b[j] = Bs[kk][tx * 4 + j];
#pragma unroll
            for (int i = 0; i < 4; i++)
#pragma unroll
                for (int j = 0; j < 4; j++)
                    acc[i][j] = fmaf(a[i], b[j], acc[i][j]);
        }
        __syncthreads();
    }

#pragma unroll
    for (int i = 0; i < 4; i++) {
        int r = row0 + ty * 4 + i;
#pragma unroll
        for (int j = 0; j < 4; j++) {
            int c = col0 + tx * 4 + j;
            float v = acc[i][j];
            if (bias) v += bias[c];
            C[(size_t)r * N + c] = v;
        }
    }
}

// ---------------------------------------------------------------------------
// RoPE + LayerNorm epilogue.
// grid = B*N blocks; block = 512 threads = 16 warps, one warp per head.
// Lane l owns dims (l, l+32) — the rotary half-pair shares one frequency.
// ---------------------------------------------------------------------------
__global__ void __launch_bounds__(512) rope_ln_kernel(
    const float* __restrict__ ln_g, const float* __restrict__ ln_b)
{
    int bn = blockIdx.x;
    int n  = bn % N_;
    int b  = bn / N_;
    int w  = threadIdx.x >> 5;      // head
    int l  = threadIdx.x & 31;      // lane

    const float* qr = g_qbuf  + (size_t)bn * DIM_ + w * D_;
    const float* kr = g_kvbuf + (size_t)bn * DIM_ + w * D_;
    float q0 = qr[l], q1 = qr[l + 32];
    float k0 = kr[l], k1 = kr[l + 32];

    // inv freq in double for accuracy: 10000^(-(2l)/64)
    double invd = pow(10000.0, -(double)(2 * l) / 64.0);
    float arg = (float)((double)n * invd);
    float s, c;
    sincosf(arg, &s, &c);

    float qa = q0 * c - q1 * s;
    float qb = q1 * c + q0 * s;
    float ka = k0 * c - k1 * s;
    float kb = k1 * c + k0 * s;

    // LayerNorm over 64 values of this head (2 per lane)
    float sum = ka + kb;
#pragma unroll
    for (int o = 16; o; o >>= 1) sum += __shfl_xor_sync(0xffffffffu, sum, o);
    float mu = sum * (1.0f / 64.0f);
    float da = ka - mu, db = kb - mu;
    float ss = da * da + db * db;
#pragma unroll
    for (int o = 16; o; o >>= 1) ss += __shfl_xor_sync(0xffffffffu, ss, o);
    float r = rsqrtf(ss * (1.0f / 64.0f) + LN_EPS_);

    float ga = ln_g[l], gb = ln_g[l + 32];
    float ba = ln_b[l], bb = ln_b[l + 32];

    size_t base = ((size_t)(b * H_ + w) * N_ + n) * D_;
    g_qs [base + l]      = qa * SCALE_;
    g_qs [base + l + 32] = qb * SCALE_;
    g_lkv[base + l]      = da * r * ga + ba;
    g_lkv[base + l + 32] = db * r * gb + bb;
}

// ---------------------------------------------------------------------------
// Latent attention (flash-style, online softmax).
// grid = (LAT/128, BH), block = 128 threads, one latent query per thread.
// Keys streamed in 64-wide smem tiles; broadcast reads.
// Causal mask only among latent keys: key j in [CTX,N) allowed iff j-CTX <= i.
// ---------------------------------------------------------------------------
__global__ void __launch_bounds__(128) latent_attn_kernel()
{
    int bh = blockIdx.y;
    int i  = blockIdx.x * 128 + threadIdx.x;   // latent index 0..1023

    const float* qrow = g_qs + ((size_t)bh * N_ + CTX_ + i) * D_;
    float q[64];
#pragma unroll
    for (int d = 0; d < 64; d++) q[d] = qrow[d];
    float o[64];
#pragma unroll
    for (int d = 0; d < 64; d++) o[d] = 0.f;
    float m = -3.0e38f, l = 0.f;

    __shared__ float Ks[64][64];
    const float* kvb = g_lkv + (size_t)bh * N_ * D_;

    for (int j0 = 0; j0 < N_; j0 += 64) {
        __syncthreads();
#pragma unroll
        for (int t = 0; t < 32; t++) {
            int idx = threadIdx.x + t * 128;       // 0..4095
            Ks[idx >> 6][idx & 63] = kvb[(size_t)j0 * 64 + idx];
        }
        __syncthreads();

        if (j0 <= CTX_ + i) {                       // tile has allowed keys
            for (int jj = 0; jj < 64; jj++) {
                int j = j0 + jj;
                if (j >= CTX_ && (j - CTX_) > i) break;  // keys ascending
                float s0 = 0.f, s1 = 0.f, s2 = 0.f, s3 = 0.f;
#pragma unroll
                for (int d = 0; d < 64; d += 4) {
                    s0 = fmaf(q[d],     Ks[jj][d],     s0);
                    s1 = fmaf(q[d + 1], Ks[jj][d + 1], s1);
                    s2 = fmaf(q[d + 2], Ks[jj][d + 2], s2);
                    s3 = fmaf(q[d + 3], Ks[jj][d + 3], s3);
                }
                float sc = (s0 + s1) + (s2 + s3);
                if (sc > m) {
                    float corr = __expf(m - sc);
                    l *= corr;
#pragma unroll
                    for (int d = 0; d < 64; d++) o[d] *= corr;
                    m = sc;
                }
                float p = __expf(sc - m);
                l += p;
#pragma unroll
                for (int d = 0; d < 64; d++) o[d] = fmaf(p, Ks[jj][d], o[d]);
            }
        }
    }

    float invl = 1.0f / l;
    int b = bh / H_, h = bh % H_;
    float* dst = g_attn + ((size_t)(b * N_ + CTX_ + i)) * DIM_ + h * D_;
#pragma unroll
    for (int d = 0; d < 64; d++) dst[d] = o[d] * invl;
}

// ---------------------------------------------------------------------------
// Context attention: block-diagonal per segment, non-causal.
// grid = (SEG, BH), block = 256 threads, one query per thread.
// ---------------------------------------------------------------------------
__global__ void __launch_bounds__(256) ctx_attn_kernel()
{
    int bh  = blockIdx.y;
    int seg = blockIdx.x;
    int qi  = threadIdx.x;               // 0..255
    int n   = seg * CHUNK_ + qi;         // global token (< CTX)

    const float* qrow = g_qs + ((size_t)bh * N_ + n) * D_;
    float q[64];
#pragma unroll
    for (int d = 0; d < 64; d++) q[d] = qrow[d];
    float o[64];
#pragma unroll
    for (int d = 0; d < 64; d++) o[d] = 0.f;
    float m = -3.0e38f, l = 0.f;

    __shared__ float Ks[64][64];
    const float* kvb = g_lkv + ((size_t)bh * N_ + seg * CHUNK_) * D_;

    for (int j0 = 0; j0 < CHUNK_; j0 += 64) {
        __syncthreads();
#pragma unroll
        for (int t = 0; t < 16; t++) {
            int idx = threadIdx.x + t * 256;  // 0..4095
            Ks[idx >> 6][idx & 63] = kvb[(size_t)j0 * 64 + idx];
        }
        __syncthreads();

        for (int jj = 0; jj < 64; jj++) {
            float s0 = 0.f, s1 = 0.f, s2 = 0.f, s3 = 0.f;
#pragma unroll
            for (int d = 0; d < 64; d += 4) {
                s0 = fmaf(q[d],     Ks[jj][d],     s0);
                s1 = fmaf(q[d + 1], Ks[jj][d + 1], s1);
                s2 = fmaf(q[d + 2], Ks[jj][d + 2], s2);
                s3 = fmaf(q[d + 3], Ks[jj][d + 3], s3);
            }
            float sc = (s0 + s1) + (s2 + s3);
            if (sc > m) {
                float corr = __expf(m - sc);
                l *= corr;
#pragma unroll
                for (int d = 0; d < 64; d++) o[d] *= corr;
                m = sc;
            }
            float p = __expf(sc - m);
            l += p;
#pragma unroll
            for (int d = 0; d < 64; d++) o[d] = fmaf(p, Ks[jj][d], o[d]);
        }
    }

    float invl = 1.0f / l;
    int b = bh / H_, h = bh % H_;
    float* dst = g_attn + ((size_t)(b * N_ + n)) * DIM_ + h * D_;
#pragma unroll
    for (int d = 0; d < 64; d++) dst[d] = o[d] * invl;
}

// ---------------------------------------------------------------------------
// Launch
// ---------------------------------------------------------------------------
extern "C" void kernel_launch(void* const* d_in, const int* in_sizes, int n_in,
                              void* d_out, int out_size)
{
    const float* x   = (const float*)d_in[0];
    const float* Wq  = (const float*)d_in[1];
    const float* Wkv = (const float*)d_in[2];
    const float* Wo  = (const float*)d_in[3];
    const float* bo  = (const float*)d_in[4];
    const float* lng = (const float*)d_in[5];
    const float* lnb = (const float*)d_in[6];
    float* out = (float*)d_out;

    float *qbuf, *kvbuf, *attn;
    cudaGetSymbolAddress((void**)&qbuf,  g_qbuf);
    cudaGetSymbolAddress((void**)&kvbuf, g_kvbuf);
    cudaGetSymbolAddress((void**)&attn,  g_attn);

    dim3 gemm_grid(DIM_ / 64, M_ / 64);   // (16, 128)

    sgemm_kernel<<<gemm_grid, 256>>>(x, Wq,  nullptr, qbuf,  M_, DIM_, DIM_);
    sgemm_kernel<<<gemm_grid, 256>>>(x, Wkv, nullptr, kvbuf, M_, DIM_, DIM_);
    rope_ln_kernel<<<M_, 512>>>(lng, lnb);
    latent_attn_kernel<<<dim3(LAT_ / 128, BH_), 128>>>();
    ctx_attn_kernel<<<dim3(SEG_, BH_), 256>>>();
    sgemm_kernel<<<gemm_grid, 256>>>(attn, Wo, bo, out, M_, DIM_, DIM_);
}

// round 3
// speedup vs baseline: 1.1269x; 1.1269x over previous
#include <cuda_runtime.h>
#include <math.h>

// Problem constants
#define B_     2
#define N_     4096
#define DIM_   1024
#define H_     16
#define D_     64
#define LAT_   1024
#define CTX_   3072
#define SEG_   12
#define CHUNK_ 256
#define BH_    (B_ * H_)          // 32
#define M_     (B_ * N_)          // 8192 rows
#define SCALE_ 0.125f             // 64^-0.5
#define LN_EPS_ 1e-5f

// ---------------------------------------------------------------------------
// Scratch (static device globals: allocation-free per harness rules)
// ---------------------------------------------------------------------------
__device__ float g_qbuf [M_ * DIM_];        // x @ Wq          [B,N,DIM]
__device__ float g_kvbuf[M_ * DIM_];        // x @ Wkv         [B,N,DIM]
__device__ float g_qs   [BH_ * N_ * D_];    // rope(q)*scale   [(BH),N,D]
__device__ float g_lkv  [BH_ * N_ * D_];    // LN(rope(kv))    [(BH),N,D]
__device__ float g_attn [M_ * DIM_];        // merged attn out [B,N,DIM]

// ---------------------------------------------------------------------------
// Tiled fp32 GEMM: C[M,N] = A[M,K] @ W[K,N] (+ bias)
// 128x128 tile, BK=16, 256 threads, 8x8 per thread, float4 everywhere.
// ---------------------------------------------------------------------------
__global__ void __launch_bounds__(256) sgemm128_kernel(
    const float* __restrict__ A, const float* __restrict__ W,
    const float* __restrict__ bias, float* __restrict__ C,
    int M, int N, int K)
{
    __shared__ float As[16][128];   // transposed A tile: As[k][m]
    __shared__ float Bs[16][128];   // Bs[k][n]

    int tid  = threadIdx.x;
    int row0 = blockIdx.y * 128, col0 = blockIdx.x * 128;
    int tm = tid & 15, tn = tid >> 4;

    int ar = tid >> 2;
    int ac = (tid & 3) * 4;
    int br = tid >> 5;
    int bc = (tid & 31) * 4;

    float acc[8][8] = {};

    for (int k0 = 0; k0 < K; k0 += 16) {
#pragma unroll
        for (int t = 0; t < 2; t++) {
            int r = ar + t * 64;
            float4 v = *(const float4*)&A[(size_t)(row0 + r) * K + k0 + ac];
            As[ac + 0][r] = v.x; As[ac + 1][r] = v.y;
            As[ac + 2][r] = v.z; As[ac + 3][r] = v.w;
        }
#pragma unroll
        for (int t = 0; t < 2; t++) {
            int r = br + t * 8;
            *(float4*)&Bs[r][bc] =
                *(const float4*)&W[(size_t)(k0 + r) * N + col0 + bc];
        }
        __syncthreads();

#pragma unroll
        for (int kk = 0; kk < 16; kk++) {
            float a[8], b[8];
            *(float4*)&a[0] = *(float4*)&As[kk][tm * 4];
            *(float4*)&a[4] = *(float4*)&As[kk][tm * 4 + 64];
            *(float4*)&b[0] = *(float4*)&Bs[kk][tn * 4];
            *(float4*)&b[4] = *(float4*)&Bs[kk][tn * 4 + 64];
#pragma unroll
            for (int i = 0; i < 8; i++)
#pragma unroll
                for (int j = 0; j < 8; j++)
                    acc[i][j] = fmaf(a[i], b[j], acc[i][j]);
        }
        __syncthreads();
    }

#pragma unroll
    for (int ih = 0; ih < 2; ih++) {
#pragma unroll
        for (int ii = 0; ii < 4; ii++) {
            int r = row0 + tm * 4 + ih * 64 + ii;
#pragma unroll
            for (int jh = 0; jh < 2; jh++) {
                int c = col0 + tn * 4 + jh * 64;
                float4 v;
                v.x = acc[ih * 4 + ii][jh * 4 + 0];
                v.y = acc[ih * 4 + ii][jh * 4 + 1];
                v.z = acc[ih * 4 + ii][jh * 4 + 2];
                v.w = acc[ih * 4 + ii][jh * 4 + 3];
                if (bias) {
                    v.x += bias[c + 0]; v.y += bias[c + 1];
                    v.z += bias[c + 2]; v.w += bias[c + 3];
                }
                *(float4*)&C[(size_t)r * N + c] = v;
            }
        }
    }
}

// ---------------------------------------------------------------------------
// RoPE + LayerNorm epilogue.
// grid = B*N blocks; block = 512 threads = 16 warps, one warp per head.
// ---------------------------------------------------------------------------
__global__ void __launch_bounds__(512) rope_ln_kernel(
    const float* __restrict__ ln_g, const float* __restrict__ ln_b)
{
    int bn = blockIdx.x;
    int n  = bn % N_;
    int b  = bn / N_;
    int w  = threadIdx.x >> 5;      // head
    int l  = threadIdx.x & 31;      // lane

    const float* qr = g_qbuf  + (size_t)bn * DIM_ + w * D_;
    const float* kr = g_kvbuf + (size_t)bn * DIM_ + w * D_;
    float q0 = qr[l], q1 = qr[l + 32];
    float k0 = kr[l], k1 = kr[l + 32];

    double invd = pow(10000.0, -(double)(2 * l) / 64.0);
    float arg = (float)((double)n * invd);
    float s, c;
    sincosf(arg, &s, &c);

    float qa = q0 * c - q1 * s;
    float qb = q1 * c + q0 * s;
    float ka = k0 * c - k1 * s;
    float kb = k1 * c + k0 * s;

    float sum = ka + kb;
#pragma unroll
    for (int o = 16; o; o >>= 1) sum += __shfl_xor_sync(0xffffffffu, sum, o);
    float mu = sum * (1.0f / 64.0f);
    float da = ka - mu, db = kb - mu;
    float ss = da * da + db * db;
#pragma unroll
    for (int o = 16; o; o >>= 1) ss += __shfl_xor_sync(0xffffffffu, ss, o);
    float r = rsqrtf(ss * (1.0f / 64.0f) + LN_EPS_);

    float ga = ln_g[l], gb = ln_g[l + 32];
    float ba = ln_b[l], bb = ln_b[l + 32];

    size_t base = ((size_t)(b * H_ + w) * N_ + n) * D_;
    g_qs [base + l]      = qa * SCALE_;
    g_qs [base + l + 32] = qb * SCALE_;
    g_lkv[base + l]      = da * r * ga + ba;
    g_lkv[base + l + 32] = db * r * gb + bb;
}

// ---------------------------------------------------------------------------
// Latent attention, split-D: 2 threads per query (32 dims each).
// grid = (LAT/128, BH), block = 256 threads (128 queries).
// Score combine uses a PAIR-scoped shuffle mask: the two lanes of a pair
// share the same query index (identical trip counts), so the shuffle is
// always convergent even though pairs diverge in loop length.
// ---------------------------------------------------------------------------
__global__ void __launch_bounds__(256) latent_attn_kernel()
{
    int bh   = blockIdx.y;
    int ql   = threadIdx.x >> 1;        // local query 0..127
    int half = threadIdx.x & 1;         // which 32-dim half
    int i    = blockIdx.x * 128 + ql;   // latent index 0..1023
    unsigned pmask = 3u << (threadIdx.x & 30);   // this pair's lanes only

    const float4* qrow = (const float4*)
        (g_qs + ((size_t)bh * N_ + CTX_ + i) * D_ + half * 32);
    float4 q[8];
#pragma unroll
    for (int d = 0; d < 8; d++) q[d] = qrow[d];
    float4 o[8];
#pragma unroll
    for (int d = 0; d < 8; d++) o[d] = make_float4(0.f, 0.f, 0.f, 0.f);
    float m = -3.0e38f, l = 0.f;

    __shared__ float Ks[64][64];        // 64 keys x 64 dims
    const float4* kvb = (const float4*)(g_lkv + (size_t)bh * N_ * D_);

    for (int j0 = 0; j0 < N_; j0 += 64) {
        __syncthreads();
#pragma unroll
        for (int t = 0; t < 4; t++) {
            int idx = threadIdx.x + t * 256;          // 0..1023 float4s
            ((float4*)Ks)[idx] = kvb[(size_t)j0 * 16 + idx];
        }
        __syncthreads();

        if (j0 <= CTX_ + i) {
            int jmax = 64;
            int lim = CTX_ + i + 1 - j0;
            if (lim < 64) jmax = lim;

            for (int jj = 0; jj < jmax; jj++) {
                const float4* krow = (const float4*)&Ks[jj][half * 32];
                float s0 = 0.f, s1 = 0.f, s2 = 0.f, s3 = 0.f;
#pragma unroll
                for (int d = 0; d < 8; d++) {
                    float4 kv = krow[d];
                    s0 = fmaf(q[d].x, kv.x, s0);
                    s1 = fmaf(q[d].y, kv.y, s1);
                    s2 = fmaf(q[d].z, kv.z, s2);
                    s3 = fmaf(q[d].w, kv.w, s3);
                }
                float sc = (s0 + s1) + (s2 + s3);
                sc += __shfl_xor_sync(pmask, sc, 1);
                if (sc > m) {
                    float corr = __expf(m - sc);
                    l *= corr;
#pragma unroll
                    for (int d = 0; d < 8; d++) {
                        o[d].x *= corr; o[d].y *= corr;
                        o[d].z *= corr; o[d].w *= corr;
                    }
                    m = sc;
                }
                float p = __expf(sc - m);
                l += p;
#pragma unroll
                for (int d = 0; d < 8; d++) {
                    float4 kv = krow[d];
                    o[d].x = fmaf(p, kv.x, o[d].x);
                    o[d].y = fmaf(p, kv.y, o[d].y);
                    o[d].z = fmaf(p, kv.z, o[d].z);
                    o[d].w = fmaf(p, kv.w, o[d].w);
                }
            }
        }
    }

    float invl = 1.0f / l;
    int b = bh / H_, h = bh % H_;
    float4* dst = (float4*)
        (g_attn + ((size_t)(b * N_ + CTX_ + i)) * DIM_ + h * D_ + half * 32);
#pragma unroll
    for (int d = 0; d < 8; d++) {
        float4 v = o[d];
        v.x *= invl; v.y *= invl; v.z *= invl; v.w *= invl;
        dst[d] = v;
    }
}

// ---------------------------------------------------------------------------
// Context attention, split-D: 2 threads per query; block = 512 threads
// (256 queries = one full segment). Non-causal block-diagonal.
// ---------------------------------------------------------------------------
__global__ void __launch_bounds__(512) ctx_attn_kernel()
{
    int bh   = blockIdx.y;
    int seg  = blockIdx.x;
    int qi   = threadIdx.x >> 1;        // 0..255
    int half = threadIdx.x & 1;
    int n    = seg * CHUNK_ + qi;
    unsigned pmask = 3u << (threadIdx.x & 30);

    const float4* qrow = (const float4*)
        (g_qs + ((size_t)bh * N_ + n) * D_ + half * 32);
    float4 q[8];
#pragma unroll
    for (int d = 0; d < 8; d++) q[d] = qrow[d];
    float4 o[8];
#pragma unroll
    for (int d = 0; d < 8; d++) o[d] = make_float4(0.f, 0.f, 0.f, 0.f);
    float m = -3.0e38f, l = 0.f;

    __shared__ float Ks[64][64];
    const float4* kvb = (const float4*)
        (g_lkv + ((size_t)bh * N_ + seg * CHUNK_) * D_);

    for (int j0 = 0; j0 < CHUNK_; j0 += 64) {
        __syncthreads();
#pragma unroll
        for (int t = 0; t < 2; t++) {
            int idx = threadIdx.x + t * 512;          // 0..1023 float4s
            ((float4*)Ks)[idx] = kvb[(size_t)j0 * 16 + idx];
        }
        __syncthreads();

        for (int jj = 0; jj < 64; jj++) {
            const float4* krow = (const float4*)&Ks[jj][half * 32];
            float s0 = 0.f, s1 = 0.f, s2 = 0.f, s3 = 0.f;
#pragma unroll
            for (int d = 0; d < 8; d++) {
                float4 kv = krow[d];
                s0 = fmaf(q[d].x, kv.x, s0);
                s1 = fmaf(q[d].y, kv.y, s1);
                s2 = fmaf(q[d].z, kv.z, s2);
                s3 = fmaf(q[d].w, kv.w, s3);
            }
            float sc = (s0 + s1) + (s2 + s3);
            sc += __shfl_xor_sync(pmask, sc, 1);
            if (sc > m) {
                float corr = __expf(m - sc);
                l *= corr;
#pragma unroll
                for (int d = 0; d < 8; d++) {
                    o[d].x *= corr; o[d].y *= corr;
                    o[d].z *= corr; o[d].w *= corr;
                }
                m = sc;
            }
            float p = __expf(sc - m);
            l += p;
#pragma unroll
            for (int d = 0; d < 8; d++) {
                float4 kv = krow[d];
                o[d].x = fmaf(p, kv.x, o[d].x);
                o[d].y = fmaf(p, kv.y, o[d].y);
                o[d].z = fmaf(p, kv.z, o[d].z);
                o[d].w = fmaf(p, kv.w, o[d].w);
            }
        }
    }

    float invl = 1.0f / l;
    int b = bh / H_, h = bh % H_;
    float4* dst = (float4*)
        (g_attn + ((size_t)(b * N_ + n)) * DIM_ + h * D_ + half * 32);
#pragma unroll
    for (int d = 0; d < 8; d++) {
        float4 v = o[d];
        v.x *= invl; v.y *= invl; v.z *= invl; v.w *= invl;
        dst[d] = v;
    }
}

// ---------------------------------------------------------------------------
// Launch
// ---------------------------------------------------------------------------
extern "C" void kernel_launch(void* const* d_in, const int* in_sizes, int n_in,
                              void* d_out, int out_size)
{
    const float* x   = (const float*)d_in[0];
    const float* Wq  = (const float*)d_in[1];
    const float* Wkv = (const float*)d_in[2];
    const float* Wo  = (const float*)d_in[3];
    const float* bo  = (const float*)d_in[4];
    const float* lng = (const float*)d_in[5];
    const float* lnb = (const float*)d_in[6];
    float* out = (float*)d_out;

    float *qbuf, *kvbuf, *attn;
    cudaGetSymbolAddress((void**)&qbuf,  g_qbuf);
    cudaGetSymbolAddress((void**)&kvbuf, g_kvbuf);
    cudaGetSymbolAddress((void**)&attn,  g_attn);

    dim3 gemm_grid(DIM_ / 128, M_ / 128);   // (8, 64)

    sgemm128_kernel<<<gemm_grid, 256>>>(x, Wq,  nullptr, qbuf,  M_, DIM_, DIM_);
    sgemm128_kernel<<<gemm_grid, 256>>>(x, Wkv, nullptr, kvbuf, M_, DIM_, DIM_);
    rope_ln_kernel<<<M_, 512>>>(lng, lnb);
    latent_attn_kernel<<<dim3(LAT_ / 128, BH_), 128 * 2>>>();
    ctx_attn_kernel<<<dim3(SEG_, BH_), 512>>>();
    sgemm128_kernel<<<gemm_grid, 256>>>(attn, Wo, bo, out, M_, DIM_, DIM_);
}

// round 4
// speedup vs baseline: 1.2818x; 1.1375x over previous
#include <cuda_runtime.h>
#include <math.h>

// Problem constants
#define B_     2
#define N_     4096
#define DIM_   1024
#define H_     16
#define D_     64
#define LAT_   1024
#define CTX_   3072
#define SEG_   12
#define CHUNK_ 256
#define BH_    (B_ * H_)          // 32
#define M_     (B_ * N_)          // 8192 rows
#define SCALE_ 0.125f             // 64^-0.5
#define LN_EPS_ 1e-5f
#define SPAD   68                 // padded smem row (floats)

// ---------------------------------------------------------------------------
// Scratch
// ---------------------------------------------------------------------------
__device__ float g_qbuf [M_ * DIM_];
__device__ float g_kvbuf[M_ * DIM_];
__device__ float g_qs   [BH_ * N_ * D_];
__device__ float g_lkv  [BH_ * N_ * D_];
__device__ float g_attn [M_ * DIM_];

// ---------------------------------------------------------------------------
// Tiled fp32 GEMM: 128x128 tile, BK=16, 256 threads, 8x8/thread (unchanged).
// ---------------------------------------------------------------------------
__global__ void __launch_bounds__(256) sgemm128_kernel(
    const float* __restrict__ A, const float* __restrict__ W,
    const float* __restrict__ bias, float* __restrict__ C,
    int M, int N, int K)
{
    __shared__ float As[16][128];
    __shared__ float Bs[16][128];

    int tid  = threadIdx.x;
    int row0 = blockIdx.y * 128, col0 = blockIdx.x * 128;
    int tm = tid & 15, tn = tid >> 4;

    int ar = tid >> 2;
    int ac = (tid & 3) * 4;
    int br = tid >> 5;
    int bc = (tid & 31) * 4;

    float acc[8][8] = {};

    for (int k0 = 0; k0 < K; k0 += 16) {
#pragma unroll
        for (int t = 0; t < 2; t++) {
            int r = ar + t * 64;
            float4 v = *(const float4*)&A[(size_t)(row0 + r) * K + k0 + ac];
            As[ac + 0][r] = v.x; As[ac + 1][r] = v.y;
            As[ac + 2][r] = v.z; As[ac + 3][r] = v.w;
        }
#pragma unroll
        for (int t = 0; t < 2; t++) {
            int r = br + t * 8;
            *(float4*)&Bs[r][bc] =
                *(const float4*)&W[(size_t)(k0 + r) * N + col0 + bc];
        }
        __syncthreads();

#pragma unroll
        for (int kk = 0; kk < 16; kk++) {
            float a[8], b[8];
            *(float4*)&a[0] = *(float4*)&As[kk][tm * 4];
            *(float4*)&a[4] = *(float4*)&As[kk][tm * 4 + 64];
            *(float4*)&b[0] = *(float4*)&Bs[kk][tn * 4];
            *(float4*)&b[4] = *(float4*)&Bs[kk][tn * 4 + 64];
#pragma unroll
            for (int i = 0; i < 8; i++)
#pragma unroll
                for (int j = 0; j < 8; j++)
                    acc[i][j] = fmaf(a[i], b[j], acc[i][j]);
        }
        __syncthreads();
    }

#pragma unroll
    for (int ih = 0; ih < 2; ih++) {
#pragma unroll
        for (int ii = 0; ii < 4; ii++) {
            int r = row0 + tm * 4 + ih * 64 + ii;
#pragma unroll
            for (int jh = 0; jh < 2; jh++) {
                int c = col0 + tn * 4 + jh * 64;
                float4 v;
                v.x = acc[ih * 4 + ii][jh * 4 + 0];
                v.y = acc[ih * 4 + ii][jh * 4 + 1];
                v.z = acc[ih * 4 + ii][jh * 4 + 2];
                v.w = acc[ih * 4 + ii][jh * 4 + 3];
                if (bias) {
                    v.x += bias[c + 0]; v.y += bias[c + 1];
                    v.z += bias[c + 2]; v.w += bias[c + 3];
                }
                *(float4*)&C[(size_t)r * N + c] = v;
            }
        }
    }
}

// ---------------------------------------------------------------------------
// RoPE + LayerNorm epilogue (unchanged).
// ---------------------------------------------------------------------------
__global__ void __launch_bounds__(512) rope_ln_kernel(
    const float* __restrict__ ln_g, const float* __restrict__ ln_b)
{
    int bn = blockIdx.x;
    int n  = bn % N_;
    int b  = bn / N_;
    int w  = threadIdx.x >> 5;
    int l  = threadIdx.x & 31;

    const float* qr = g_qbuf  + (size_t)bn * DIM_ + w * D_;
    const float* kr = g_kvbuf + (size_t)bn * DIM_ + w * D_;
    float q0 = qr[l], q1 = qr[l + 32];
    float k0 = kr[l], k1 = kr[l + 32];

    double invd = pow(10000.0, -(double)(2 * l) / 64.0);
    float arg = (float)((double)n * invd);
    float s, c;
    sincosf(arg, &s, &c);

    float qa = q0 * c - q1 * s;
    float qb = q1 * c + q0 * s;
    float ka = k0 * c - k1 * s;
    float kb = k1 * c + k0 * s;

    float sum = ka + kb;
#pragma unroll
    for (int o = 16; o; o >>= 1) sum += __shfl_xor_sync(0xffffffffu, sum, o);
    float mu = sum * (1.0f / 64.0f);
    float da = ka - mu, db = kb - mu;
    float ss = da * da + db * db;
#pragma unroll
    for (int o = 16; o; o >>= 1) ss += __shfl_xor_sync(0xffffffffu, ss, o);
    float r = rsqrtf(ss * (1.0f / 64.0f) + LN_EPS_);

    float ga = ln_g[l], gb = ln_g[l + 32];
    float ba = ln_b[l], bb = ln_b[l + 32];

    size_t base = ((size_t)(b * H_ + w) * N_ + n) * D_;
    g_qs [base + l]      = qa * SCALE_;
    g_qs [base + l + 32] = qb * SCALE_;
    g_lkv[base + l]      = da * r * ga + ba;
    g_lkv[base + l + 32] = db * r * gb + bb;
}

// ---------------------------------------------------------------------------
// Unified tiled flash attention (fp32 register-tiled GEMMs).
// Block = 256 threads handles a 64-query tile. Key tiles of 64.
// Thread (tq = tid>>4, tk = tid&15) owns a 4q x 4k score micro-tile and a
// 4q x 4d output micro-tile (d-range = tk*4..tk*4+3).
// q-tile index qt in [0,64): qt<48 -> context (segment-local, non-causal);
// qt>=48 -> latent (all ctx keys + causal latents). V == K (lkv).
// Dynamic smem: Qt[64][68] (Q^T), Kn[64][68] (K natural), U[64][68]
// (K^T during S-GEMM, then P^T for the O-GEMM).
// ---------------------------------------------------------------------------
extern __shared__ float smem_attn[];

__global__ void __launch_bounds__(256, 3) attn_tile_kernel()
{
    float* Qt = smem_attn;                 // [64][SPAD] Qt[d][i]
    float* Kn = smem_attn + 64 * SPAD;     // [64][SPAD] Kn[j][d]
    float* U  = smem_attn + 128 * SPAD;    // [64][SPAD] Kt[d][j] / Ps[j][i]

    int bh = blockIdx.y;
    int qt = 63 - blockIdx.x;              // heavy latent tiles first
    int q0 = qt * 64;                      // global token base of this q-tile
    bool is_lat = (q0 >= CTX_);

    int tid = threadIdx.x;
    int tq  = tid >> 4;                    // 0..15 -> queries tq*4..tq*4+3
    int tk  = tid & 15;                    // 0..15 -> keys/dims tk*4..tk*4+3

    // loader mapping: float4 f = tid + t*256 ; row = f>>4 ; c4 = f&15
    int lrow = tid >> 4;                   // rows tid>>4, +16, +32, +48
    int lc4  = tid & 15;

    // ---- load Q tile transposed: Qt[d][i] ----
    {
        const float4* src = (const float4*)(g_qs + ((size_t)bh * N_ + q0) * D_);
#pragma unroll
        for (int t = 0; t < 4; t++) {
            int row = lrow + t * 16;
            float4 v = src[row * 16 + lc4];
            int c = lc4 * 4;
            Qt[(c + 0) * SPAD + row] = v.x;
            Qt[(c + 1) * SPAD + row] = v.y;
            Qt[(c + 2) * SPAD + row] = v.z;
            Qt[(c + 3) * SPAD + row] = v.w;
        }
    }

    float m[4], l[4], o[4][4];
#pragma unroll
    for (int r = 0; r < 4; r++) {
        m[r] = -3.0e38f; l[r] = 0.f;
#pragma unroll
        for (int c = 0; c < 4; c++) o[r][c] = 0.f;
    }

    int ks, ntiles;
    if (is_lat) { ks = 0;               ntiles = qt + 1; }     // keys [0, q0+64)
    else        { ks = (q0 >> 8) << 8;  ntiles = CHUNK_ / 64; } // segment-local

    for (int t0 = 0; t0 < ntiles; t0++) {
        int kt0 = ks + t0 * 64;

        __syncthreads();   // prior O-GEMM reads of Kn/U done before overwrite

        // ---- load K tile: natural Kn[j][d] and transposed U=Kt[d][j] ----
        {
            const float4* src =
                (const float4*)(g_lkv + ((size_t)bh * N_ + kt0) * D_);
#pragma unroll
            for (int t = 0; t < 4; t++) {
                int row = lrow + t * 16;
                float4 v = src[row * 16 + lc4];
                *(float4*)&Kn[row * SPAD + lc4 * 4] = v;
                int c = lc4 * 4;
                U[(c + 0) * SPAD + row] = v.x;
                U[(c + 1) * SPAD + row] = v.y;
                U[(c + 2) * SPAD + row] = v.z;
                U[(c + 3) * SPAD + row] = v.w;
            }
        }
        __syncthreads();

        // ---- S = Q . K^T  (contraction over d) ----
        float s[4][4] = {};
#pragma unroll
        for (int kk = 0; kk < 64; kk++) {
            float4 a4 = *(float4*)&Qt[kk * SPAD + tq * 4];
            float4 b4 = *(float4*)&U [kk * SPAD + tk * 4];
            float a[4] = {a4.x, a4.y, a4.z, a4.w};
            float b[4] = {b4.x, b4.y, b4.z, b4.w};
#pragma unroll
            for (int r = 0; r < 4; r++)
#pragma unroll
                for (int c = 0; c < 4; c++)
                    s[r][c] = fmaf(a[r], b[c], s[r][c]);
        }

        // ---- causal mask among latent keys ----
        if (is_lat && kt0 >= CTX_) {
            int L0 = q0 - CTX_;
#pragma unroll
            for (int r = 0; r < 4; r++) {
                int qi = L0 + tq * 4 + r;
#pragma unroll
                for (int c = 0; c < 4; c++) {
                    int kL = kt0 - CTX_ + tk * 4 + c;
                    if (kL > qi) s[r][c] = -3.0e38f;
                }
            }
        }

        // ---- online softmax (per q-row, across the 16 tk threads) ----
        float p[4][4];
        float rsum[4];
#pragma unroll
        for (int r = 0; r < 4; r++) {
            float rmax = fmaxf(fmaxf(s[r][0], s[r][1]), fmaxf(s[r][2], s[r][3]));
#pragma unroll
            for (int off = 8; off; off >>= 1)
                rmax = fmaxf(rmax, __shfl_xor_sync(0xffffffffu, rmax, off));
            float mnew = fmaxf(m[r], rmax);
            float corr = __expf(m[r] - mnew);
            m[r] = mnew;
            float rs = 0.f;
#pragma unroll
            for (int c = 0; c < 4; c++) {
                p[r][c] = __expf(s[r][c] - mnew);
                rs += p[r][c];
            }
#pragma unroll
            for (int off = 8; off; off >>= 1)
                rs += __shfl_xor_sync(0xffffffffu, rs, off);
            rsum[r] = rs;
            l[r] = l[r] * corr + rs;
#pragma unroll
            for (int c = 0; c < 4; c++) o[r][c] *= corr;
        }
        (void)rsum;

        __syncthreads();   // all S-GEMM reads of U(Kt) done before P^T store

        // ---- store P^T into U: Ps[j][i] ----
#pragma unroll
        for (int c = 0; c < 4; c++)
#pragma unroll
            for (int r = 0; r < 4; r++)
                U[(tk * 4 + c) * SPAD + tq * 4 + r] = p[r][c];

        __syncthreads();

        // ---- O += P . K  (contraction over keys j) ----
#pragma unroll
        for (int jj = 0; jj < 64; jj++) {
            float4 a4 = *(float4*)&U [jj * SPAD + tq * 4];
            float4 b4 = *(float4*)&Kn[jj * SPAD + tk * 4];
            float a[4] = {a4.x, a4.y, a4.z, a4.w};
            float b[4] = {b4.x, b4.y, b4.z, b4.w};
#pragma unroll
            for (int r = 0; r < 4; r++)
#pragma unroll
                for (int c = 0; c < 4; c++)
                    o[r][c] = fmaf(a[r], b[c], o[r][c]);
        }
    }

    // ---- write merged output: g_attn[b, token, h*64 + tk*4 ..] ----
    int b = bh / H_, h = bh % H_;
#pragma unroll
    for (int r = 0; r < 4; r++) {
        float inv = 1.0f / l[r];
        int token = q0 + tq * 4 + r;
        float4 v;
        v.x = o[r][0] * inv; v.y = o[r][1] * inv;
        v.z = o[r][2] * inv; v.w = o[r][3] * inv;
        *(float4*)&g_attn[((size_t)(b * N_ + token)) * DIM_ + h * D_ + tk * 4] = v;
    }
}

// ---------------------------------------------------------------------------
// Launch
// ---------------------------------------------------------------------------
extern "C" void kernel_launch(void* const* d_in, const int* in_sizes, int n_in,
                              void* d_out, int out_size)
{
    const float* x   = (const float*)d_in[0];
    const float* Wq  = (const float*)d_in[1];
    const float* Wkv = (const float*)d_in[2];
    const float* Wo  = (const float*)d_in[3];
    const float* bo  = (const float*)d_in[4];
    const float* lng = (const float*)d_in[5];
    const float* lnb = (const float*)d_in[6];
    float* out = (float*)d_out;

    float *qbuf, *kvbuf, *attn;
    cudaGetSymbolAddress((void**)&qbuf,  g_qbuf);
    cudaGetSymbolAddress((void**)&kvbuf, g_kvbuf);
    cudaGetSymbolAddress((void**)&attn,  g_attn);

    static int attn_smem_set = 0;
    int attn_smem = 3 * 64 * SPAD * (int)sizeof(float);   // 52,224 B
    if (!attn_smem_set) {
        cudaFuncSetAttribute(attn_tile_kernel,
                             cudaFuncAttributeMaxDynamicSharedMemorySize,
                             attn_smem);
        attn_smem_set = 1;
    }

    dim3 gemm_grid(DIM_ / 128, M_ / 128);   // (8, 64)

    sgemm128_kernel<<<gemm_grid, 256>>>(x, Wq,  nullptr, qbuf,  M_, DIM_, DIM_);
    sgemm128_kernel<<<gemm_grid, 256>>>(x, Wkv, nullptr, kvbuf, M_, DIM_, DIM_);
    rope_ln_kernel<<<M_, 512>>>(lng, lnb);
    attn_tile_kernel<<<dim3(64, BH_), 256, attn_smem>>>();
    sgemm128_kernel<<<gemm_grid, 256>>>(attn, Wo, bo, out, M_, DIM_, DIM_);
}

// round 6
// speedup vs baseline: 1.4540x; 1.1343x over previous
#include <cuda_runtime.h>
#include <math.h>

// Problem constants
#define B_     2
#define N_     4096
#define DIM_   1024
#define H_     16
#define D_     64
#define LAT_   1024
#define CTX_   3072
#define SEG_   12
#define CHUNK_ 256
#define BH_    (B_ * H_)
#define M_     (B_ * N_)
#define SCALE_ 0.125f
#define LN_EPS_ 1e-5f
#define SPAD   68

// tf32 GEMM tiling
#define BM   128
#define BN   128
#define BKK  32
#define KP   36
#define NP   136
#define ASTAGE (BM * KP)
#define BSTAGE (BKK * NP)

// ---------------------------------------------------------------------------
// Scratch
// ---------------------------------------------------------------------------
__device__ float g_qbuf [M_ * DIM_];
__device__ float g_kvbuf[M_ * DIM_];
__device__ float g_qs   [BH_ * N_ * D_];
__device__ float g_lkv  [BH_ * N_ * D_];
__device__ float g_attn [M_ * DIM_];

// ---------------------------------------------------------------------------
// 3xTF32 tensor-core GEMM: C[M,N] = A[M,K] @ W[K,N] (+bias), ~fp32 accuracy.
// Each operand split exactly: hi = bits & 0xFFFFE000 (tf32-exact),
// lo = x - hi. acc += a_hi*b_hi + a_lo*b_hi + a_hi*b_lo.
// ---------------------------------------------------------------------------
__device__ __forceinline__ void mma_tf32(float (&d)[4],
                                         const unsigned (&a)[4],
                                         const unsigned (&b)[2])
{
    asm volatile(
        "mma.sync.aligned.m16n8k8.row.col.f32.tf32.tf32.f32 "
        "{%0,%1,%2,%3}, {%4,%5,%6,%7}, {%8,%9}, {%0,%1,%2,%3};\n"
        : "+f"(d[0]), "+f"(d[1]), "+f"(d[2]), "+f"(d[3])
        : "r"(a[0]), "r"(a[1]), "r"(a[2]), "r"(a[3]),
          "r"(b[0]), "r"(b[1]));
}

__device__ __forceinline__ void split_hl(float x, unsigned& hi, unsigned& lo)
{
    unsigned xb = __float_as_uint(x);
    hi = xb & 0xFFFFE000u;                       // exact tf32 head
    lo = __float_as_uint(x - __uint_as_float(hi)); // exact residual
}

__device__ __forceinline__ void cp16(void* smem_dst, const void* gsrc)
{
    unsigned dst = (unsigned)__cvta_generic_to_shared(smem_dst);
    asm volatile("cp.async.cg.shared.global [%0], [%1], 16;\n"
                 :: "r"(dst), "l"(gsrc));
}

extern __shared__ float sm_gemm[];

__global__ void __launch_bounds__(256) tf32gemm_kernel(
    const float* __restrict__ A, const float* __restrict__ W,
    const float* __restrict__ bias, float* __restrict__ C,
    int M, int N, int K)
{
    float* As = sm_gemm;
    float* Bs = sm_gemm + 2 * ASTAGE;

    int tid  = threadIdx.x;
    int wid  = tid >> 5, lane = tid & 31;
    int wm   = wid >> 2, wn = wid & 3;
    int g    = lane >> 2, t = lane & 3;
    int row0 = blockIdx.y * BM, col0 = blockIdx.x * BN;

    float acc[4][4][4] = {};

    const int NIT = K / BKK;

    auto issue = [&](int it, int stage) {
        int k0 = it * BKK;
#pragma unroll
        for (int i = 0; i < 4; i++) {
            int cidx = tid + i * 256;
            int r = cidx >> 3, c4 = cidx & 7;
            cp16(As + stage * ASTAGE + r * KP + c4 * 4,
                 A + (size_t)(row0 + r) * K + k0 + c4 * 4);
        }
#pragma unroll
        for (int i = 0; i < 4; i++) {
            int cidx = tid + i * 256;
            int r = cidx >> 5, c4 = cidx & 31;
            cp16(Bs + stage * BSTAGE + r * NP + c4 * 4,
                 W + (size_t)(k0 + r) * N + col0 + c4 * 4);
        }
        asm volatile("cp.async.commit_group;\n");
    };

    issue(0, 0);

    for (int it = 0; it < NIT; it++) {
        int stage = it & 1;
        if (it + 1 < NIT) {
            issue(it + 1, (it + 1) & 1);
            asm volatile("cp.async.wait_group 1;\n");
        } else {
            asm volatile("cp.async.wait_group 0;\n");
        }
        __syncthreads();

        const float* a_s = As + stage * ASTAGE + (wm * 64) * KP;
        const float* b_s = Bs + stage * BSTAGE + wn * 32;

#pragma unroll
        for (int ks = 0; ks < 4; ks++) {
            int k0 = ks * 8;
            unsigned ah[4][4], al[4][4];
            unsigned bh[4][2], bl[4][2];
#pragma unroll
            for (int mi = 0; mi < 4; mi++) {
                const float* ap  = a_s + (mi * 16 + g) * KP + k0 + t;
                const float* ap8 = ap + 8 * KP;
                split_hl(ap [0], ah[mi][0], al[mi][0]);
                split_hl(ap8[0], ah[mi][1], al[mi][1]);
                split_hl(ap [4], ah[mi][2], al[mi][2]);
                split_hl(ap8[4], ah[mi][3], al[mi][3]);
            }
#pragma unroll
            for (int ni = 0; ni < 4; ni++) {
                const float* bp = b_s + (k0 + t) * NP + ni * 8 + g;
                split_hl(bp[0],      bh[ni][0], bl[ni][0]);
                split_hl(bp[4 * NP], bh[ni][1], bl[ni][1]);
            }
#pragma unroll
            for (int mi = 0; mi < 4; mi++)
#pragma unroll
                for (int ni = 0; ni < 4; ni++) {
                    mma_tf32(acc[mi][ni], al[mi], bh[ni]);  // lo*hi
                    mma_tf32(acc[mi][ni], ah[mi], bl[ni]);  // hi*lo
                    mma_tf32(acc[mi][ni], ah[mi], bh[ni]);  // hi*hi
                }
        }
        __syncthreads();
    }

#pragma unroll
    for (int mi = 0; mi < 4; mi++) {
        int r0 = row0 + wm * 64 + mi * 16 + g;
#pragma unroll
        for (int ni = 0; ni < 4; ni++) {
            int c = col0 + wn * 32 + ni * 8 + 2 * t;
            float bx = 0.f, by = 0.f;
            if (bias) { bx = bias[c]; by = bias[c + 1]; }
            float2 v0 = {acc[mi][ni][0] + bx, acc[mi][ni][1] + by};
            *(float2*)&C[(size_t)r0 * N + c] = v0;
            float2 v1 = {acc[mi][ni][2] + bx, acc[mi][ni][3] + by};
            *(float2*)&C[(size_t)(r0 + 8) * N + c] = v1;
        }
    }
}

// ---------------------------------------------------------------------------
// RoPE + LayerNorm epilogue (unchanged).
// ---------------------------------------------------------------------------
__global__ void __launch_bounds__(512) rope_ln_kernel(
    const float* __restrict__ ln_g, const float* __restrict__ ln_b)
{
    int bn = blockIdx.x;
    int n  = bn % N_;
    int b  = bn / N_;
    int w  = threadIdx.x >> 5;
    int l  = threadIdx.x & 31;

    const float* qr = g_qbuf  + (size_t)bn * DIM_ + w * D_;
    const float* kr = g_kvbuf + (size_t)bn * DIM_ + w * D_;
    float q0 = qr[l], q1 = qr[l + 32];
    float k0 = kr[l], k1 = kr[l + 32];

    double invd = pow(10000.0, -(double)(2 * l) / 64.0);
    float arg = (float)((double)n * invd);
    float s, c;
    sincosf(arg, &s, &c);

    float qa = q0 * c - q1 * s;
    float qb = q1 * c + q0 * s;
    float ka = k0 * c - k1 * s;
    float kb = k1 * c + k0 * s;

    float sum = ka + kb;
#pragma unroll
    for (int o = 16; o; o >>= 1) sum += __shfl_xor_sync(0xffffffffu, sum, o);
    float mu = sum * (1.0f / 64.0f);
    float da = ka - mu, db = kb - mu;
    float ss = da * da + db * db;
#pragma unroll
    for (int o = 16; o; o >>= 1) ss += __shfl_xor_sync(0xffffffffu, ss, o);
    float r = rsqrtf(ss * (1.0f / 64.0f) + LN_EPS_);

    float ga = ln_g[l], gb = ln_g[l + 32];
    float ba = ln_b[l], bb = ln_b[l + 32];

    size_t base = ((size_t)(b * H_ + w) * N_ + n) * D_;
    g_qs [base + l]      = qa * SCALE_;
    g_qs [base + l + 32] = qb * SCALE_;
    g_lkv[base + l]      = da * r * ga + ba;
    g_lkv[base + l + 32] = db * r * gb + bb;
}

// ---------------------------------------------------------------------------
// Unified tiled flash attention (unchanged).
// ---------------------------------------------------------------------------
extern __shared__ float smem_attn[];

__global__ void __launch_bounds__(256, 3) attn_tile_kernel()
{
    float* Qt = smem_attn;
    float* Kn = smem_attn + 64 * SPAD;
    float* U  = smem_attn + 128 * SPAD;

    int bh = blockIdx.y;
    int qt = 63 - blockIdx.x;
    int q0 = qt * 64;
    bool is_lat = (q0 >= CTX_);

    int tid = threadIdx.x;
    int tq  = tid >> 4;
    int tk  = tid & 15;

    int lrow = tid >> 4;
    int lc4  = tid & 15;

    {
        const float4* src = (const float4*)(g_qs + ((size_t)bh * N_ + q0) * D_);
#pragma unroll
        for (int t = 0; t < 4; t++) {
            int row = lrow + t * 16;
            float4 v = src[row * 16 + lc4];
            int c = lc4 * 4;
            Qt[(c + 0) * SPAD + row] = v.x;
            Qt[(c + 1) * SPAD + row] = v.y;
            Qt[(c + 2) * SPAD + row] = v.z;
            Qt[(c + 3) * SPAD + row] = v.w;
        }
    }

    float m[4], l[4], o[4][4];
#pragma unroll
    for (int r = 0; r < 4; r++) {
        m[r] = -3.0e38f; l[r] = 0.f;
#pragma unroll
        for (int c = 0; c < 4; c++) o[r][c] = 0.f;
    }

    int ks, ntiles;
    if (is_lat) { ks = 0;               ntiles = qt + 1; }
    else        { ks = (q0 >> 8) << 8;  ntiles = CHUNK_ / 64; }

    for (int t0 = 0; t0 < ntiles; t0++) {
        int kt0 = ks + t0 * 64;

        __syncthreads();

        {
            const float4* src =
                (const float4*)(g_lkv + ((size_t)bh * N_ + kt0) * D_);
#pragma unroll
            for (int t = 0; t < 4; t++) {
                int row = lrow + t * 16;
                float4 v = src[row * 16 + lc4];
                *(float4*)&Kn[row * SPAD + lc4 * 4] = v;
                int c = lc4 * 4;
                U[(c + 0) * SPAD + row] = v.x;
                U[(c + 1) * SPAD + row] = v.y;
                U[(c + 2) * SPAD + row] = v.z;
                U[(c + 3) * SPAD + row] = v.w;
            }
        }
        __syncthreads();

        float s[4][4] = {};
#pragma unroll
        for (int kk = 0; kk < 64; kk++) {
            float4 a4 = *(float4*)&Qt[kk * SPAD + tq * 4];
            float4 b4 = *(float4*)&U [kk * SPAD + tk * 4];
            float a[4] = {a4.x, a4.y, a4.z, a4.w};
            float b[4] = {b4.x, b4.y, b4.z, b4.w};
#pragma unroll
            for (int r = 0; r < 4; r++)
#pragma unroll
                for (int c = 0; c < 4; c++)
                    s[r][c] = fmaf(a[r], b[c], s[r][c]);
        }

        if (is_lat && kt0 >= CTX_) {
            int L0 = q0 - CTX_;
#pragma unroll
            for (int r = 0; r < 4; r++) {
                int qi = L0 + tq * 4 + r;
#pragma unroll
                for (int c = 0; c < 4; c++) {
                    int kL = kt0 - CTX_ + tk * 4 + c;
                    if (kL > qi) s[r][c] = -3.0e38f;
                }
            }
        }

        float p[4][4];
#pragma unroll
        for (int r = 0; r < 4; r++) {
            float rmax = fmaxf(fmaxf(s[r][0], s[r][1]), fmaxf(s[r][2], s[r][3]));
#pragma unroll
            for (int off = 8; off; off >>= 1)
                rmax = fmaxf(rmax, __shfl_xor_sync(0xffffffffu, rmax, off));
            float mnew = fmaxf(m[r], rmax);
            float corr = __expf(m[r] - mnew);
            m[r] = mnew;
            float rs = 0.f;
#pragma unroll
            for (int c = 0; c < 4; c++) {
                p[r][c] = __expf(s[r][c] - mnew);
                rs += p[r][c];
            }
#pragma unroll
            for (int off = 8; off; off >>= 1)
                rs += __shfl_xor_sync(0xffffffffu, rs, off);
            l[r] = l[r] * corr + rs;
#pragma unroll
            for (int c = 0; c < 4; c++) o[r][c] *= corr;
        }

        __syncthreads();

#pragma unroll
        for (int c = 0; c < 4; c++)
#pragma unroll
            for (int r = 0; r < 4; r++)
                U[(tk * 4 + c) * SPAD + tq * 4 + r] = p[r][c];

        __syncthreads();

#pragma unroll
        for (int jj = 0; jj < 64; jj++) {
            float4 a4 = *(float4*)&U [jj * SPAD + tq * 4];
            float4 b4 = *(float4*)&Kn[jj * SPAD + tk * 4];
            float a[4] = {a4.x, a4.y, a4.z, a4.w};
            float b[4] = {b4.x, b4.y, b4.z, b4.w};
#pragma unroll
            for (int r = 0; r < 4; r++)
#pragma unroll
                for (int c = 0; c < 4; c++)
                    o[r][c] = fmaf(a[r], b[c], o[r][c]);
        }
    }

    int b = bh / H_, h = bh % H_;
#pragma unroll
    for (int r = 0; r < 4; r++) {
        float inv = 1.0f / l[r];
        int token = q0 + tq * 4 + r;
        float4 v;
        v.x = o[r][0] * inv; v.y = o[r][1] * inv;
        v.z = o[r][2] * inv; v.w = o[r][3] * inv;
        *(float4*)&g_attn[((size_t)(b * N_ + token)) * DIM_ + h * D_ + tk * 4] = v;
    }
}

// ---------------------------------------------------------------------------
// Launch
// ---------------------------------------------------------------------------
extern "C" void kernel_launch(void* const* d_in, const int* in_sizes, int n_in,
                              void* d_out, int out_size)
{
    const float* x   = (const float*)d_in[0];
    const float* Wq  = (const float*)d_in[1];
    const float* Wkv = (const float*)d_in[2];
    const float* Wo  = (const float*)d_in[3];
    const float* bo  = (const float*)d_in[4];
    const float* lng = (const float*)d_in[5];
    const float* lnb = (const float*)d_in[6];
    float* out = (float*)d_out;

    float *qbuf, *kvbuf, *attn;
    cudaGetSymbolAddress((void**)&qbuf,  g_qbuf);
    cudaGetSymbolAddress((void**)&kvbuf, g_kvbuf);
    cudaGetSymbolAddress((void**)&attn,  g_attn);

    int attn_smem = 3 * 64 * SPAD * (int)sizeof(float);
    int gemm_smem = 2 * (ASTAGE + BSTAGE) * (int)sizeof(float);

    static int attr_set = 0;
    if (!attr_set) {
        cudaFuncSetAttribute(attn_tile_kernel,
                             cudaFuncAttributeMaxDynamicSharedMemorySize,
                             attn_smem);
        cudaFuncSetAttribute(tf32gemm_kernel,
                             cudaFuncAttributeMaxDynamicSharedMemorySize,
                             gemm_smem);
        attr_set = 1;
    }

    dim3 gemm_grid(DIM_ / BN, M_ / BM);

    tf32gemm_kernel<<<gemm_grid, 256, gemm_smem>>>(x, Wq,  nullptr, qbuf,  M_, DIM_, DIM_);
    tf32gemm_kernel<<<gemm_grid, 256, gemm_smem>>>(x, Wkv, nullptr, kvbuf, M_, DIM_, DIM_);
    rope_ln_kernel<<<M_, 512>>>(lng, lnb);
    attn_tile_kernel<<<dim3(64, BH_), 256, attn_smem>>>();
    tf32gemm_kernel<<<gemm_grid, 256, gemm_smem>>>(attn, Wo, bo, out, M_, DIM_, DIM_);
}

// round 7
// speedup vs baseline: 1.7470x; 1.2015x over previous
#include <cuda_runtime.h>
#include <math.h>

// Problem constants
#define B_     2
#define N_     4096
#define DIM_   1024
#define H_     16
#define D_     64
#define LAT_   1024
#define CTX_   3072
#define SEG_   12
#define CHUNK_ 256
#define BH_    (B_ * H_)
#define M_     (B_ * N_)
#define SCALE_ 0.125f
#define LN_EPS_ 1e-5f

// tf32 GEMM tiling
#define BM   128
#define BN   128
#define BKK  32
#define KP   36
#define NP   136
#define ASTAGE (BM * KP)
#define BSTAGE (BKK * NP)

// attention smem pitch
#define PQ   68

// ---------------------------------------------------------------------------
// Scratch
// ---------------------------------------------------------------------------
__device__ float g_qbuf [M_ * DIM_];
__device__ float g_kvbuf[M_ * DIM_];
__device__ float g_qs   [BH_ * N_ * D_];
__device__ float g_lkv  [BH_ * N_ * D_];
__device__ float g_attn [M_ * DIM_];

// ---------------------------------------------------------------------------
// mma + split helpers (shared by GEMM and attention)
// ---------------------------------------------------------------------------
__device__ __forceinline__ void mma_tf32(float (&d)[4],
                                         const unsigned (&a)[4],
                                         const unsigned (&b)[2])
{
    asm volatile(
        "mma.sync.aligned.m16n8k8.row.col.f32.tf32.tf32.f32 "
        "{%0,%1,%2,%3}, {%4,%5,%6,%7}, {%8,%9}, {%0,%1,%2,%3};\n"
        : "+f"(d[0]), "+f"(d[1]), "+f"(d[2]), "+f"(d[3])
        : "r"(a[0]), "r"(a[1]), "r"(a[2]), "r"(a[3]),
          "r"(b[0]), "r"(b[1]));
}

__device__ __forceinline__ void split_hl(float x, unsigned& hi, unsigned& lo)
{
    unsigned xb = __float_as_uint(x);
    hi = xb & 0xFFFFE000u;
    lo = __float_as_uint(x - __uint_as_float(hi));
}

__device__ __forceinline__ void cp16(void* smem_dst, const void* gsrc)
{
    unsigned dst = (unsigned)__cvta_generic_to_shared(smem_dst);
    asm volatile("cp.async.cg.shared.global [%0], [%1], 16;\n"
                 :: "r"(dst), "l"(gsrc));
}

// ---------------------------------------------------------------------------
// 3xTF32 tensor-core GEMM (unchanged from round 6).
// ---------------------------------------------------------------------------
extern __shared__ float sm_gemm[];

__global__ void __launch_bounds__(256) tf32gemm_kernel(
    const float* __restrict__ A, const float* __restrict__ W,
    const float* __restrict__ bias, float* __restrict__ C,
    int M, int N, int K)
{
    float* As = sm_gemm;
    float* Bs = sm_gemm + 2 * ASTAGE;

    int tid  = threadIdx.x;
    int wid  = tid >> 5, lane = tid & 31;
    int wm   = wid >> 2, wn = wid & 3;
    int g    = lane >> 2, t = lane & 3;
    int row0 = blockIdx.y * BM, col0 = blockIdx.x * BN;

    float acc[4][4][4] = {};
    const int NIT = K / BKK;

    auto issue = [&](int it, int stage) {
        int k0 = it * BKK;
#pragma unroll
        for (int i = 0; i < 4; i++) {
            int cidx = tid + i * 256;
            int r = cidx >> 3, c4 = cidx & 7;
            cp16(As + stage * ASTAGE + r * KP + c4 * 4,
                 A + (size_t)(row0 + r) * K + k0 + c4 * 4);
        }
#pragma unroll
        for (int i = 0; i < 4; i++) {
            int cidx = tid + i * 256;
            int r = cidx >> 5, c4 = cidx & 31;
            cp16(Bs + stage * BSTAGE + r * NP + c4 * 4,
                 W + (size_t)(k0 + r) * N + col0 + c4 * 4);
        }
        asm volatile("cp.async.commit_group;\n");
    };

    issue(0, 0);

    for (int it = 0; it < NIT; it++) {
        int stage = it & 1;
        if (it + 1 < NIT) {
            issue(it + 1, (it + 1) & 1);
            asm volatile("cp.async.wait_group 1;\n");
        } else {
            asm volatile("cp.async.wait_group 0;\n");
        }
        __syncthreads();

        const float* a_s = As + stage * ASTAGE + (wm * 64) * KP;
        const float* b_s = Bs + stage * BSTAGE + wn * 32;

#pragma unroll
        for (int ks = 0; ks < 4; ks++) {
            int k0 = ks * 8;
            unsigned ah[4][4], al[4][4];
            unsigned bh[4][2], bl[4][2];
#pragma unroll
            for (int mi = 0; mi < 4; mi++) {
                const float* ap  = a_s + (mi * 16 + g) * KP + k0 + t;
                const float* ap8 = ap + 8 * KP;
                split_hl(ap [0], ah[mi][0], al[mi][0]);
                split_hl(ap8[0], ah[mi][1], al[mi][1]);
                split_hl(ap [4], ah[mi][2], al[mi][2]);
                split_hl(ap8[4], ah[mi][3], al[mi][3]);
            }
#pragma unroll
            for (int ni = 0; ni < 4; ni++) {
                const float* bp = b_s + (k0 + t) * NP + ni * 8 + g;
                split_hl(bp[0],      bh[ni][0], bl[ni][0]);
                split_hl(bp[4 * NP], bh[ni][1], bl[ni][1]);
            }
#pragma unroll
            for (int mi = 0; mi < 4; mi++)
#pragma unroll
                for (int ni = 0; ni < 4; ni++) {
                    mma_tf32(acc[mi][ni], al[mi], bh[ni]);
                    mma_tf32(acc[mi][ni], ah[mi], bl[ni]);
                    mma_tf32(acc[mi][ni], ah[mi], bh[ni]);
                }
        }
        __syncthreads();
    }

#pragma unroll
    for (int mi = 0; mi < 4; mi++) {
        int r0 = row0 + wm * 64 + mi * 16 + g;
#pragma unroll
        for (int ni = 0; ni < 4; ni++) {
            int c = col0 + wn * 32 + ni * 8 + 2 * t;
            float bx = 0.f, by = 0.f;
            if (bias) { bx = bias[c]; by = bias[c + 1]; }
            float2 v0 = {acc[mi][ni][0] + bx, acc[mi][ni][1] + by};
            *(float2*)&C[(size_t)r0 * N + c] = v0;
            float2 v1 = {acc[mi][ni][2] + bx, acc[mi][ni][3] + by};
            *(float2*)&C[(size_t)(r0 + 8) * N + c] = v1;
        }
    }
}

// ---------------------------------------------------------------------------
// RoPE + LayerNorm epilogue (unchanged).
// ---------------------------------------------------------------------------
__global__ void __launch_bounds__(512) rope_ln_kernel(
    const float* __restrict__ ln_g, const float* __restrict__ ln_b)
{
    int bn = blockIdx.x;
    int n  = bn % N_;
    int b  = bn / N_;
    int w  = threadIdx.x >> 5;
    int l  = threadIdx.x & 31;

    const float* qr = g_qbuf  + (size_t)bn * DIM_ + w * D_;
    const float* kr = g_kvbuf + (size_t)bn * DIM_ + w * D_;
    float q0 = qr[l], q1 = qr[l + 32];
    float k0 = kr[l], k1 = kr[l + 32];

    double invd = pow(10000.0, -(double)(2 * l) / 64.0);
    float arg = (float)((double)n * invd);
    float s, c;
    sincosf(arg, &s, &c);

    float qa = q0 * c - q1 * s;
    float qb = q1 * c + q0 * s;
    float ka = k0 * c - k1 * s;
    float kb = k1 * c + k0 * s;

    float sum = ka + kb;
#pragma unroll
    for (int o = 16; o; o >>= 1) sum += __shfl_xor_sync(0xffffffffu, sum, o);
    float mu = sum * (1.0f / 64.0f);
    float da = ka - mu, db = kb - mu;
    float ss = da * da + db * db;
#pragma unroll
    for (int o = 16; o; o >>= 1) ss += __shfl_xor_sync(0xffffffffu, ss, o);
    float r = rsqrtf(ss * (1.0f / 64.0f) + LN_EPS_);

    float ga = ln_g[l], gb = ln_g[l + 32];
    float ba = ln_b[l], bb = ln_b[l + 32];

    size_t base = ((size_t)(b * H_ + w) * N_ + n) * D_;
    g_qs [base + l]      = qa * SCALE_;
    g_qs [base + l + 32] = qb * SCALE_;
    g_lkv[base + l]      = da * r * ga + ba;
    g_lkv[base + l + 32] = db * r * gb + bb;
}

// ---------------------------------------------------------------------------
// Tensorized flash attention: S = Q.K^T and O += P.K via 3xTF32 mma.sync.
// CTA = 64-query tile of one (b,h). 8 warps: wm=wid>>1 (16 q-rows each),
// wn=wid&1 (32 keys / 32 dims each). Softmax fp32, cross-warp via smem.
// smem: Qs[64][PQ], Kt[64][PQ] (d-major), Kn[64][PQ] (k-major), Ps[64][PQ],
//       redm[2][64], reds[2][64].
// ---------------------------------------------------------------------------
extern __shared__ float sm_attn[];

__global__ void __launch_bounds__(256, 2) attn_mma_kernel()
{
    float* Qs   = sm_attn;
    float* Kt   = sm_attn + 64 * PQ;
    float* Kn   = sm_attn + 128 * PQ;
    float* Ps   = sm_attn + 192 * PQ;
    float* redm = sm_attn + 256 * PQ;          // [2][64]
    float* reds = redm + 128;                  // [2][64]

    int bh = blockIdx.y;
    int qt = 63 - blockIdx.x;                  // latent tiles first
    int q0 = qt * 64;
    bool is_lat = (q0 >= CTX_);

    int tid  = threadIdx.x;
    int wid  = tid >> 5, lane = tid & 31;
    int wm   = wid >> 1, wn = wid & 1;
    int g    = lane >> 2, t = lane & 3;

    int row0 = wm * 16 + g;                    // local q row (and row0+8)
    int lrow = tid >> 4, lc4 = tid & 15;       // tile loader mapping

    // ---- load Q tile (row-major [q][d]) ----
    {
        const float4* src = (const float4*)(g_qs + ((size_t)bh * N_ + q0) * D_);
#pragma unroll
        for (int it = 0; it < 4; it++) {
            int row = lrow + it * 16;
            *(float4*)&Qs[row * PQ + lc4 * 4] = src[row * 16 + lc4];
        }
    }

    float s[4][4];
    float o[4][4] = {};
    float m0 = -3.0e38f, m1 = -3.0e38f, l0 = 0.f, l1 = 0.f;

    int ks0, ntiles;
    if (is_lat) { ks0 = 0;               ntiles = qt + 1; }
    else        { ks0 = (q0 >> 8) << 8;  ntiles = CHUNK_ / 64; }

    for (int t0 = 0; t0 < ntiles; t0++) {
        int kt0 = ks0 + t0 * 64;

        __syncthreads();   // prior O-GEMM reads of Kn + Q visibility (1st iter)

        // ---- load K tile: Kn[j][d] natural, Kt[d][j] transposed ----
        {
            const float4* src =
                (const float4*)(g_lkv + ((size_t)bh * N_ + kt0) * D_);
#pragma unroll
            for (int it = 0; it < 4; it++) {
                int row = lrow + it * 16;
                float4 v = src[row * 16 + lc4];
                *(float4*)&Kn[row * PQ + lc4 * 4] = v;
                int c = lc4 * 4;
                Kt[(c + 0) * PQ + row] = v.x;
                Kt[(c + 1) * PQ + row] = v.y;
                Kt[(c + 2) * PQ + row] = v.z;
                Kt[(c + 3) * PQ + row] = v.w;
            }
        }
        __syncthreads();

        // ---- S = Q . K^T  (A = Qs rows wm*16.., B = Kt [d][k]) ----
#pragma unroll
        for (int ni = 0; ni < 4; ni++)
#pragma unroll
            for (int e = 0; e < 4; e++) s[ni][e] = 0.f;

#pragma unroll
        for (int ks = 0; ks < 8; ks++) {
            int k0 = ks * 8;
            unsigned ah[4], al[4], bh2[4][2], bl2[4][2];
            const float* ap  = Qs + row0 * PQ + k0 + t;
            const float* ap8 = ap + 8 * PQ;
            split_hl(ap [0], ah[0], al[0]);
            split_hl(ap8[0], ah[1], al[1]);
            split_hl(ap [4], ah[2], al[2]);
            split_hl(ap8[4], ah[3], al[3]);
#pragma unroll
            for (int ni = 0; ni < 4; ni++) {
                const float* bp = Kt + (k0 + t) * PQ + wn * 32 + ni * 8 + g;
                split_hl(bp[0],      bh2[ni][0], bl2[ni][0]);
                split_hl(bp[4 * PQ], bh2[ni][1], bl2[ni][1]);
            }
#pragma unroll
            for (int ni = 0; ni < 4; ni++) {
                mma_tf32(s[ni], al, bh2[ni]);
                mma_tf32(s[ni], ah, bl2[ni]);
                mma_tf32(s[ni], ah, bh2[ni]);
            }
        }

        // ---- causal mask among latent keys ----
        if (is_lat && kt0 >= CTX_) {
#pragma unroll
            for (int ni = 0; ni < 4; ni++) {
                int col = wn * 32 + ni * 8 + 2 * t;
                // global condition: kt0 + col > q0 + row
                if (kt0 + col     > q0 + row0)     s[ni][0] = -3.0e38f;
                if (kt0 + col + 1 > q0 + row0)     s[ni][1] = -3.0e38f;
                if (kt0 + col     > q0 + row0 + 8) s[ni][2] = -3.0e38f;
                if (kt0 + col + 1 > q0 + row0 + 8) s[ni][3] = -3.0e38f;
            }
        }

        // ---- softmax part 1: row max (quad + cross-warp) ----
        float mx0 = -3.0e38f, mx1 = -3.0e38f;
#pragma unroll
        for (int ni = 0; ni < 4; ni++) {
            mx0 = fmaxf(mx0, fmaxf(s[ni][0], s[ni][1]));
            mx1 = fmaxf(mx1, fmaxf(s[ni][2], s[ni][3]));
        }
        mx0 = fmaxf(mx0, __shfl_xor_sync(0xffffffffu, mx0, 1));
        mx0 = fmaxf(mx0, __shfl_xor_sync(0xffffffffu, mx0, 2));
        mx1 = fmaxf(mx1, __shfl_xor_sync(0xffffffffu, mx1, 1));
        mx1 = fmaxf(mx1, __shfl_xor_sync(0xffffffffu, mx1, 2));
        if (t == 0) {
            redm[wn * 64 + row0]     = mx0;
            redm[wn * 64 + row0 + 8] = mx1;
        }
        __syncthreads();

        float gm0 = fmaxf(redm[row0],     redm[64 + row0]);
        float gm1 = fmaxf(redm[row0 + 8], redm[64 + row0 + 8]);
        float mn0 = fmaxf(m0, gm0), mn1 = fmaxf(m1, gm1);
        float corr0 = __expf(m0 - mn0), corr1 = __expf(m1 - mn1);
        m0 = mn0; m1 = mn1;

        // ---- exp + row sum + store P ----
        float rs0 = 0.f, rs1 = 0.f;
#pragma unroll
        for (int ni = 0; ni < 4; ni++) {
            int col = wn * 32 + ni * 8 + 2 * t;
            float p0 = __expf(s[ni][0] - m0);
            float p1 = __expf(s[ni][1] - m0);
            float p2 = __expf(s[ni][2] - m1);
            float p3 = __expf(s[ni][3] - m1);
            rs0 += p0 + p1;
            rs1 += p2 + p3;
            *(float2*)&Ps[row0 * PQ + col]       = make_float2(p0, p1);
            *(float2*)&Ps[(row0 + 8) * PQ + col] = make_float2(p2, p3);
        }
        rs0 += __shfl_xor_sync(0xffffffffu, rs0, 1);
        rs0 += __shfl_xor_sync(0xffffffffu, rs0, 2);
        rs1 += __shfl_xor_sync(0xffffffffu, rs1, 1);
        rs1 += __shfl_xor_sync(0xffffffffu, rs1, 2);
        if (t == 0) {
            reds[wn * 64 + row0]     = rs0;
            reds[wn * 64 + row0 + 8] = rs1;
        }

        // rescale running O
#pragma unroll
        for (int ni = 0; ni < 4; ni++) {
            o[ni][0] *= corr0; o[ni][1] *= corr0;
            o[ni][2] *= corr1; o[ni][3] *= corr1;
        }
        __syncthreads();

        l0 = l0 * corr0 + reds[row0]     + reds[64 + row0];
        l1 = l1 * corr1 + reds[row0 + 8] + reds[64 + row0 + 8];

        // ---- O += P . K  (A = Ps rows wm*16.., B = Kn [j][d]) ----
#pragma unroll
        for (int ks = 0; ks < 8; ks++) {
            int k0 = ks * 8;
            unsigned ah[4], al[4], bh2[4][2], bl2[4][2];
            const float* ap  = Ps + row0 * PQ + k0 + t;
            const float* ap8 = ap + 8 * PQ;
            split_hl(ap [0], ah[0], al[0]);
            split_hl(ap8[0], ah[1], al[1]);
            split_hl(ap [4], ah[2], al[2]);
            split_hl(ap8[4], ah[3], al[3]);
#pragma unroll
            for (int ni = 0; ni < 4; ni++) {
                const float* bp = Kn + (k0 + t) * PQ + wn * 32 + ni * 8 + g;
                split_hl(bp[0],      bh2[ni][0], bl2[ni][0]);
                split_hl(bp[4 * PQ], bh2[ni][1], bl2[ni][1]);
            }
#pragma unroll
            for (int ni = 0; ni < 4; ni++) {
                mma_tf32(o[ni], al, bh2[ni]);
                mma_tf32(o[ni], ah, bl2[ni]);
                mma_tf32(o[ni], ah, bh2[ni]);
            }
        }
    }

    // ---- epilogue ----
    float inv0 = 1.0f / l0, inv1 = 1.0f / l1;
    int b = bh / H_, h = bh % H_;
    int tok0 = q0 + row0;
#pragma unroll
    for (int ni = 0; ni < 4; ni++) {
        int col = h * D_ + wn * 32 + ni * 8 + 2 * t;
        float2 v0 = make_float2(o[ni][0] * inv0, o[ni][1] * inv0);
        *(float2*)&g_attn[((size_t)(b * N_ + tok0)) * DIM_ + col] = v0;
        float2 v1 = make_float2(o[ni][2] * inv1, o[ni][3] * inv1);
        *(float2*)&g_attn[((size_t)(b * N_ + tok0 + 8)) * DIM_ + col] = v1;
    }
}

// ---------------------------------------------------------------------------
// Launch
// ---------------------------------------------------------------------------
extern "C" void kernel_launch(void* const* d_in, const int* in_sizes, int n_in,
                              void* d_out, int out_size)
{
    const float* x   = (const float*)d_in[0];
    const float* Wq  = (const float*)d_in[1];
    const float* Wkv = (const float*)d_in[2];
    const float* Wo  = (const float*)d_in[3];
    const float* bo  = (const float*)d_in[4];
    const float* lng = (const float*)d_in[5];
    const float* lnb = (const float*)d_in[6];
    float* out = (float*)d_out;

    float *qbuf, *kvbuf, *attn;
    cudaGetSymbolAddress((void**)&qbuf,  g_qbuf);
    cudaGetSymbolAddress((void**)&kvbuf, g_kvbuf);
    cudaGetSymbolAddress((void**)&attn,  g_attn);

    int attn_smem = (256 * PQ + 256) * (int)sizeof(float);      // 70,656 B
    int gemm_smem = 2 * (ASTAGE + BSTAGE) * (int)sizeof(float); // 71,680 B

    static int attr_set = 0;
    if (!attr_set) {
        cudaFuncSetAttribute(attn_mma_kernel,
                             cudaFuncAttributeMaxDynamicSharedMemorySize,
                             attn_smem);
        cudaFuncSetAttribute(tf32gemm_kernel,
                             cudaFuncAttributeMaxDynamicSharedMemorySize,
                             gemm_smem);
        attr_set = 1;
    }

    dim3 gemm_grid(DIM_ / BN, M_ / BM);

    tf32gemm_kernel<<<gemm_grid, 256, gemm_smem>>>(x, Wq,  nullptr, qbuf,  M_, DIM_, DIM_);
    tf32gemm_kernel<<<gemm_grid, 256, gemm_smem>>>(x, Wkv, nullptr, kvbuf, M_, DIM_, DIM_);
    rope_ln_kernel<<<M_, 512>>>(lng, lnb);
    attn_mma_kernel<<<dim3(64, BH_), 256, attn_smem>>>();
    tf32gemm_kernel<<<gemm_grid, 256, gemm_smem>>>(attn, Wo, bo, out, M_, DIM_, DIM_);
}

// round 8
// speedup vs baseline: 1.8216x; 1.0427x over previous
#include <cuda_runtime.h>
#include <math.h>

// Problem constants
#define B_     2
#define N_     4096
#define DIM_   1024
#define H_     16
#define D_     64
#define LAT_   1024
#define CTX_   3072
#define SEG_   12
#define CHUNK_ 256
#define BH_    (B_ * H_)
#define M_     (B_ * N_)
#define SCALE_ 0.125f
#define LN_EPS_ 1e-5f

// tf32 GEMM tiling
#define BM   128
#define BN   128
#define BKK  32
#define KP   36
#define NP   136
#define ASTAGE (BM * KP)
#define BSTAGE (BKK * NP)

// attention smem pitch
#define PQ   68

// ---------------------------------------------------------------------------
// Scratch
// ---------------------------------------------------------------------------
__device__ float g_qbuf [M_ * DIM_];
__device__ float g_kvbuf[M_ * DIM_];
__device__ float g_qs   [BH_ * N_ * D_];
__device__ float g_lkv  [BH_ * N_ * D_];
__device__ float g_attn [M_ * DIM_];

// ---------------------------------------------------------------------------
// mma + split helpers
// ---------------------------------------------------------------------------
__device__ __forceinline__ void mma_tf32(float (&d)[4],
                                         const unsigned (&a)[4],
                                         const unsigned (&b)[2])
{
    asm volatile(
        "mma.sync.aligned.m16n8k8.row.col.f32.tf32.tf32.f32 "
        "{%0,%1,%2,%3}, {%4,%5,%6,%7}, {%8,%9}, {%0,%1,%2,%3};\n"
        : "+f"(d[0]), "+f"(d[1]), "+f"(d[2]), "+f"(d[3])
        : "r"(a[0]), "r"(a[1]), "r"(a[2]), "r"(a[3]),
          "r"(b[0]), "r"(b[1]));
}

__device__ __forceinline__ void split_hl(float x, unsigned& hi, unsigned& lo)
{
    unsigned xb = __float_as_uint(x);
    hi = xb & 0xFFFFE000u;
    lo = __float_as_uint(x - __uint_as_float(hi));
}

__device__ __forceinline__ void cp16(void* smem_dst, const void* gsrc)
{
    unsigned dst = (unsigned)__cvta_generic_to_shared(smem_dst);
    asm volatile("cp.async.cg.shared.global [%0], [%1], 16;\n"
                 :: "r"(dst), "l"(gsrc));
}

// ---------------------------------------------------------------------------
// 3xTF32 tensor-core GEMM (unchanged).
// ---------------------------------------------------------------------------
extern __shared__ float sm_gemm[];

__global__ void __launch_bounds__(256) tf32gemm_kernel(
    const float* __restrict__ A, const float* __restrict__ W,
    const float* __restrict__ bias, float* __restrict__ C,
    int M, int N, int K)
{
    float* As = sm_gemm;
    float* Bs = sm_gemm + 2 * ASTAGE;

    int tid  = threadIdx.x;
    int wid  = tid >> 5, lane = tid & 31;
    int wm   = wid >> 2, wn = wid & 3;
    int g    = lane >> 2, t = lane & 3;
    int row0 = blockIdx.y * BM, col0 = blockIdx.x * BN;

    float acc[4][4][4] = {};
    const int NIT = K / BKK;

    auto issue = [&](int it, int stage) {
        int k0 = it * BKK;
#pragma unroll
        for (int i = 0; i < 4; i++) {
            int cidx = tid + i * 256;
            int r = cidx >> 3, c4 = cidx & 7;
            cp16(As + stage * ASTAGE + r * KP + c4 * 4,
                 A + (size_t)(row0 + r) * K + k0 + c4 * 4);
        }
#pragma unroll
        for (int i = 0; i < 4; i++) {
            int cidx = tid + i * 256;
            int r = cidx >> 5, c4 = cidx & 31;
            cp16(Bs + stage * BSTAGE + r * NP + c4 * 4,
                 W + (size_t)(k0 + r) * N + col0 + c4 * 4);
        }
        asm volatile("cp.async.commit_group;\n");
    };

    issue(0, 0);

    for (int it = 0; it < NIT; it++) {
        int stage = it & 1;
        if (it + 1 < NIT) {
            issue(it + 1, (it + 1) & 1);
            asm volatile("cp.async.wait_group 1;\n");
        } else {
            asm volatile("cp.async.wait_group 0;\n");
        }
        __syncthreads();

        const float* a_s = As + stage * ASTAGE + (wm * 64) * KP;
        const float* b_s = Bs + stage * BSTAGE + wn * 32;

#pragma unroll
        for (int ks = 0; ks < 4; ks++) {
            int k0 = ks * 8;
            unsigned ah[4][4], al[4][4];
            unsigned bh[4][2], bl[4][2];
#pragma unroll
            for (int mi = 0; mi < 4; mi++) {
                const float* ap  = a_s + (mi * 16 + g) * KP + k0 + t;
                const float* ap8 = ap + 8 * KP;
                split_hl(ap [0], ah[mi][0], al[mi][0]);
                split_hl(ap8[0], ah[mi][1], al[mi][1]);
                split_hl(ap [4], ah[mi][2], al[mi][2]);
                split_hl(ap8[4], ah[mi][3], al[mi][3]);
            }
#pragma unroll
            for (int ni = 0; ni < 4; ni++) {
                const float* bp = b_s + (k0 + t) * NP + ni * 8 + g;
                split_hl(bp[0],      bh[ni][0], bl[ni][0]);
                split_hl(bp[4 * NP], bh[ni][1], bl[ni][1]);
            }
#pragma unroll
            for (int mi = 0; mi < 4; mi++)
#pragma unroll
                for (int ni = 0; ni < 4; ni++) {
                    mma_tf32(acc[mi][ni], al[mi], bh[ni]);
                    mma_tf32(acc[mi][ni], ah[mi], bl[ni]);
                    mma_tf32(acc[mi][ni], ah[mi], bh[ni]);
                }
        }
        __syncthreads();
    }

#pragma unroll
    for (int mi = 0; mi < 4; mi++) {
        int r0 = row0 + wm * 64 + mi * 16 + g;
#pragma unroll
        for (int ni = 0; ni < 4; ni++) {
            int c = col0 + wn * 32 + ni * 8 + 2 * t;
            float bx = 0.f, by = 0.f;
            if (bias) { bx = bias[c]; by = bias[c + 1]; }
            float2 v0 = {acc[mi][ni][0] + bx, acc[mi][ni][1] + by};
            *(float2*)&C[(size_t)r0 * N + c] = v0;
            float2 v1 = {acc[mi][ni][2] + bx, acc[mi][ni][3] + by};
            *(float2*)&C[(size_t)(r0 + 8) * N + c] = v1;
        }
    }
}

// ---------------------------------------------------------------------------
// RoPE + LayerNorm epilogue (unchanged).
// ---------------------------------------------------------------------------
__global__ void __launch_bounds__(512) rope_ln_kernel(
    const float* __restrict__ ln_g, const float* __restrict__ ln_b)
{
    int bn = blockIdx.x;
    int n  = bn % N_;
    int b  = bn / N_;
    int w  = threadIdx.x >> 5;
    int l  = threadIdx.x & 31;

    const float* qr = g_qbuf  + (size_t)bn * DIM_ + w * D_;
    const float* kr = g_kvbuf + (size_t)bn * DIM_ + w * D_;
    float q0 = qr[l], q1 = qr[l + 32];
    float k0 = kr[l], k1 = kr[l + 32];

    double invd = pow(10000.0, -(double)(2 * l) / 64.0);
    float arg = (float)((double)n * invd);
    float s, c;
    sincosf(arg, &s, &c);

    float qa = q0 * c - q1 * s;
    float qb = q1 * c + q0 * s;
    float ka = k0 * c - k1 * s;
    float kb = k1 * c + k0 * s;

    float sum = ka + kb;
#pragma unroll
    for (int o = 16; o; o >>= 1) sum += __shfl_xor_sync(0xffffffffu, sum, o);
    float mu = sum * (1.0f / 64.0f);
    float da = ka - mu, db = kb - mu;
    float ss = da * da + db * db;
#pragma unroll
    for (int o = 16; o; o >>= 1) ss += __shfl_xor_sync(0xffffffffu, ss, o);
    float r = rsqrtf(ss * (1.0f / 64.0f) + LN_EPS_);

    float ga = ln_g[l], gb = ln_g[l + 32];
    float ba = ln_b[l], bb = ln_b[l + 32];

    size_t base = ((size_t)(b * H_ + w) * N_ + n) * D_;
    g_qs [base + l]      = qa * SCALE_;
    g_qs [base + l + 32] = qb * SCALE_;
    g_lkv[base + l]      = da * r * ga + ba;
    g_lkv[base + l + 32] = db * r * gb + bb;
}

// ---------------------------------------------------------------------------
// Tensorized flash attention (3xTF32 mma).
// No K transpose: the S-GEMM B-fragment (B = K^T in .col layout) is read
// directly from the natural K tile Kn[key][d] at (col+g)*PQ + k0+t —
// bank-conflict-free for PQ=68. smem = Qs + Kn + Ps + reductions = 53.2 KB,
// launch_bounds(256,3) caps regs at 85 -> 3 CTAs/SM.
// ---------------------------------------------------------------------------
extern __shared__ float sm_attn[];

__global__ void __launch_bounds__(256, 3) attn_mma_kernel()
{
    float* Qs   = sm_attn;                     // [64][PQ] Q rows
    float* Kn   = sm_attn + 64 * PQ;           // [64][PQ] K rows (natural)
    float* Ps   = sm_attn + 128 * PQ;          // [64][PQ] P rows
    float* redm = sm_attn + 192 * PQ;          // [2][64]
    float* reds = redm + 128;                  // [2][64]

    int bh = blockIdx.y;
    int qt = 63 - blockIdx.x;                  // latent tiles first
    int q0 = qt * 64;
    bool is_lat = (q0 >= CTX_);

    int tid  = threadIdx.x;
    int wid  = tid >> 5, lane = tid & 31;
    int wm   = wid >> 1, wn = wid & 1;
    int g    = lane >> 2, t = lane & 3;

    int row0 = wm * 16 + g;
    int lrow = tid >> 4, lc4 = tid & 15;

    // ---- load Q tile (row-major [q][d]) ----
    {
        const float4* src = (const float4*)(g_qs + ((size_t)bh * N_ + q0) * D_);
#pragma unroll
        for (int it = 0; it < 4; it++) {
            int row = lrow + it * 16;
            *(float4*)&Qs[row * PQ + lc4 * 4] = src[row * 16 + lc4];
        }
    }

    float s[4][4];
    float o[4][4] = {};
    float m0 = -3.0e38f, m1 = -3.0e38f, l0 = 0.f, l1 = 0.f;

    int ks0, ntiles;
    if (is_lat) { ks0 = 0;               ntiles = qt + 1; }
    else        { ks0 = (q0 >> 8) << 8;  ntiles = CHUNK_ / 64; }

    for (int t0 = 0; t0 < ntiles; t0++) {
        int kt0 = ks0 + t0 * 64;

        __syncthreads();   // prior O-GEMM reads of Kn done before overwrite

        // ---- load K tile (natural layout only) ----
        {
            const float4* src =
                (const float4*)(g_lkv + ((size_t)bh * N_ + kt0) * D_);
#pragma unroll
            for (int it = 0; it < 4; it++) {
                int row = lrow + it * 16;
                *(float4*)&Kn[row * PQ + lc4 * 4] = src[row * 16 + lc4];
            }
        }
        __syncthreads();

        // ---- S = Q . K^T : B[k=d][n=key] = Kn[key][d] ----
#pragma unroll
        for (int ni = 0; ni < 4; ni++)
#pragma unroll
            for (int e = 0; e < 4; e++) s[ni][e] = 0.f;

#pragma unroll
        for (int ks = 0; ks < 8; ks++) {
            int k0 = ks * 8;
            unsigned ah[4], al[4], bh2[4][2], bl2[4][2];
            const float* ap  = Qs + row0 * PQ + k0 + t;
            const float* ap8 = ap + 8 * PQ;
            split_hl(ap [0], ah[0], al[0]);
            split_hl(ap8[0], ah[1], al[1]);
            split_hl(ap [4], ah[2], al[2]);
            split_hl(ap8[4], ah[3], al[3]);
#pragma unroll
            for (int ni = 0; ni < 4; ni++) {
                const float* bp = Kn + (wn * 32 + ni * 8 + g) * PQ + k0 + t;
                split_hl(bp[0], bh2[ni][0], bl2[ni][0]);
                split_hl(bp[4], bh2[ni][1], bl2[ni][1]);
            }
#pragma unroll
            for (int ni = 0; ni < 4; ni++) {
                mma_tf32(s[ni], al, bh2[ni]);
                mma_tf32(s[ni], ah, bl2[ni]);
                mma_tf32(s[ni], ah, bh2[ni]);
            }
        }

        // ---- causal mask among latent keys ----
        if (is_lat && kt0 >= CTX_) {
#pragma unroll
            for (int ni = 0; ni < 4; ni++) {
                int col = wn * 32 + ni * 8 + 2 * t;
                if (kt0 + col     > q0 + row0)     s[ni][0] = -3.0e38f;
                if (kt0 + col + 1 > q0 + row0)     s[ni][1] = -3.0e38f;
                if (kt0 + col     > q0 + row0 + 8) s[ni][2] = -3.0e38f;
                if (kt0 + col + 1 > q0 + row0 + 8) s[ni][3] = -3.0e38f;
            }
        }

        // ---- softmax: row max (quad + cross-warp) ----
        float mx0 = -3.0e38f, mx1 = -3.0e38f;
#pragma unroll
        for (int ni = 0; ni < 4; ni++) {
            mx0 = fmaxf(mx0, fmaxf(s[ni][0], s[ni][1]));
            mx1 = fmaxf(mx1, fmaxf(s[ni][2], s[ni][3]));
        }
        mx0 = fmaxf(mx0, __shfl_xor_sync(0xffffffffu, mx0, 1));
        mx0 = fmaxf(mx0, __shfl_xor_sync(0xffffffffu, mx0, 2));
        mx1 = fmaxf(mx1, __shfl_xor_sync(0xffffffffu, mx1, 1));
        mx1 = fmaxf(mx1, __shfl_xor_sync(0xffffffffu, mx1, 2));
        if (t == 0) {
            redm[wn * 64 + row0]     = mx0;
            redm[wn * 64 + row0 + 8] = mx1;
        }
        __syncthreads();

        float gm0 = fmaxf(redm[row0],     redm[64 + row0]);
        float gm1 = fmaxf(redm[row0 + 8], redm[64 + row0 + 8]);
        float mn0 = fmaxf(m0, gm0), mn1 = fmaxf(m1, gm1);
        float corr0 = __expf(m0 - mn0), corr1 = __expf(m1 - mn1);
        m0 = mn0; m1 = mn1;

        // ---- exp + row sum + store P ----
        float rs0 = 0.f, rs1 = 0.f;
#pragma unroll
        for (int ni = 0; ni < 4; ni++) {
            int col = wn * 32 + ni * 8 + 2 * t;
            float p0 = __expf(s[ni][0] - m0);
            float p1 = __expf(s[ni][1] - m0);
            float p2 = __expf(s[ni][2] - m1);
            float p3 = __expf(s[ni][3] - m1);
            rs0 += p0 + p1;
            rs1 += p2 + p3;
            *(float2*)&Ps[row0 * PQ + col]       = make_float2(p0, p1);
            *(float2*)&Ps[(row0 + 8) * PQ + col] = make_float2(p2, p3);
        }
        rs0 += __shfl_xor_sync(0xffffffffu, rs0, 1);
        rs0 += __shfl_xor_sync(0xffffffffu, rs0, 2);
        rs1 += __shfl_xor_sync(0xffffffffu, rs1, 1);
        rs1 += __shfl_xor_sync(0xffffffffu, rs1, 2);
        if (t == 0) {
            reds[wn * 64 + row0]     = rs0;
            reds[wn * 64 + row0 + 8] = rs1;
        }

#pragma unroll
        for (int ni = 0; ni < 4; ni++) {
            o[ni][0] *= corr0; o[ni][1] *= corr0;
            o[ni][2] *= corr1; o[ni][3] *= corr1;
        }
        __syncthreads();

        l0 = l0 * corr0 + reds[row0]     + reds[64 + row0];
        l1 = l1 * corr1 + reds[row0 + 8] + reds[64 + row0 + 8];

        // ---- O += P . K : B[k=key][n=d] = Kn[key][d] ----
#pragma unroll
        for (int ks = 0; ks < 8; ks++) {
            int k0 = ks * 8;
            unsigned ah[4], al[4], bh2[4][2], bl2[4][2];
            const float* ap  = Ps + row0 * PQ + k0 + t;
            const float* ap8 = ap + 8 * PQ;
            split_hl(ap [0], ah[0], al[0]);
            split_hl(ap8[0], ah[1], al[1]);
            split_hl(ap [4], ah[2], al[2]);
            split_hl(ap8[4], ah[3], al[3]);
#pragma unroll
            for (int ni = 0; ni < 4; ni++) {
                const float* bp = Kn + (k0 + t) * PQ + wn * 32 + ni * 8 + g;
                split_hl(bp[0],      bh2[ni][0], bl2[ni][0]);
                split_hl(bp[4 * PQ], bh2[ni][1], bl2[ni][1]);
            }
#pragma unroll
            for (int ni = 0; ni < 4; ni++) {
                mma_tf32(o[ni], al, bh2[ni]);
                mma_tf32(o[ni], ah, bl2[ni]);
                mma_tf32(o[ni], ah, bh2[ni]);
            }
        }
    }

    // ---- epilogue ----
    float inv0 = 1.0f / l0, inv1 = 1.0f / l1;
    int b = bh / H_, h = bh % H_;
    int tok0 = q0 + row0;
#pragma unroll
    for (int ni = 0; ni < 4; ni++) {
        int col = h * D_ + wn * 32 + ni * 8 + 2 * t;
        float2 v0 = make_float2(o[ni][0] * inv0, o[ni][1] * inv0);
        *(float2*)&g_attn[((size_t)(b * N_ + tok0)) * DIM_ + col] = v0;
        float2 v1 = make_float2(o[ni][2] * inv1, o[ni][3] * inv1);
        *(float2*)&g_attn[((size_t)(b * N_ + tok0 + 8)) * DIM_ + col] = v1;
    }
}

// ---------------------------------------------------------------------------
// Launch
// ---------------------------------------------------------------------------
extern "C" void kernel_launch(void* const* d_in, const int* in_sizes, int n_in,
                              void* d_out, int out_size)
{
    const float* x   = (const float*)d_in[0];
    const float* Wq  = (const float*)d_in[1];
    const float* Wkv = (const float*)d_in[2];
    const float* Wo  = (const float*)d_in[3];
    const float* bo  = (const float*)d_in[4];
    const float* lng = (const float*)d_in[5];
    const float* lnb = (const float*)d_in[6];
    float* out = (float*)d_out;

    float *qbuf, *kvbuf, *attn;
    cudaGetSymbolAddress((void**)&qbuf,  g_qbuf);
    cudaGetSymbolAddress((void**)&kvbuf, g_kvbuf);
    cudaGetSymbolAddress((void**)&attn,  g_attn);

    int attn_smem = (192 * PQ + 256) * (int)sizeof(float);      // 53,248 B
    int gemm_smem = 2 * (ASTAGE + BSTAGE) * (int)sizeof(float); // 71,680 B

    static int attr_set = 0;
    if (!attr_set) {
        cudaFuncSetAttribute(attn_mma_kernel,
                             cudaFuncAttributeMaxDynamicSharedMemorySize,
                             attn_smem);
        cudaFuncSetAttribute(tf32gemm_kernel,
                             cudaFuncAttributeMaxDynamicSharedMemorySize,
                             gemm_smem);
        attr_set = 1;
    }

    dim3 gemm_grid(DIM_ / BN, M_ / BM);

    tf32gemm_kernel<<<gemm_grid, 256, gemm_smem>>>(x, Wq,  nullptr, qbuf,  M_, DIM_, DIM_);
    tf32gemm_kernel<<<gemm_grid, 256, gemm_smem>>>(x, Wkv, nullptr, kvbuf, M_, DIM_, DIM_);
    rope_ln_kernel<<<M_, 512>>>(lng, lnb);
    attn_mma_kernel<<<dim3(64, BH_), 256, attn_smem>>>();
    tf32gemm_kernel<<<gemm_grid, 256, gemm_smem>>>(attn, Wo, bo, out, M_, DIM_, DIM_);
}

// round 9
// speedup vs baseline: 2.6111x; 1.4334x over previous
#include <cuda_runtime.h>
#include <math.h>

// Problem constants
#define B_     2
#define N_     4096
#define DIM_   1024
#define H_     16
#define D_     64
#define LAT_   1024
#define CTX_   3072
#define SEG_   12
#define CHUNK_ 256
#define BH_    (B_ * H_)
#define M_     (B_ * N_)
#define SCALE_ 0.125f
#define LN_EPS_ 1e-5f

// tf32 GEMM tiling (BM x BN x BKK = 128 x 64 x 32, 8 warps of 32x32)
#define BM    128
#define BN    64
#define BKK   32
#define KP    36      // As pitch: (4g+t)%32 distinct -> conflict-free
#define NP2   72      // Bs pitch: (8t+g)%32 distinct -> conflict-free
#define ASTG  (BM * BKK + BM * 4)     // 128*36 = 4608
#define BSTG  (BKK * NP2)             // 32*72  = 2304
#define EPIT  72      // epilogue staging pitch: (8r+j)%32 distinct

// attention smem pitch
#define PQ   68

// epilogue modes
#define EPI_BIAS 0
#define EPI_Q    1
#define EPI_KV   2

// ---------------------------------------------------------------------------
// Scratch
// ---------------------------------------------------------------------------
__device__ float g_qs   [BH_ * N_ * D_];
__device__ float g_lkv  [BH_ * N_ * D_];
__device__ float g_attn [M_ * DIM_];

// ---------------------------------------------------------------------------
// mma + split helpers
// ---------------------------------------------------------------------------
__device__ __forceinline__ void mma_tf32(float (&d)[4],
                                         const unsigned (&a)[4],
                                         const unsigned (&b)[2])
{
    asm volatile(
        "mma.sync.aligned.m16n8k8.row.col.f32.tf32.tf32.f32 "
        "{%0,%1,%2,%3}, {%4,%5,%6,%7}, {%8,%9}, {%0,%1,%2,%3};\n"
        : "+f"(d[0]), "+f"(d[1]), "+f"(d[2]), "+f"(d[3])
        : "r"(a[0]), "r"(a[1]), "r"(a[2]), "r"(a[3]),
          "r"(b[0]), "r"(b[1]));
}

__device__ __forceinline__ void split_hl(float x, unsigned& hi, unsigned& lo)
{
    unsigned xb = __float_as_uint(x);
    hi = xb & 0xFFFFE000u;
    lo = __float_as_uint(x - __uint_as_float(hi));
}

__device__ __forceinline__ void cp16(void* smem_dst, const void* gsrc)
{
    unsigned dst = (unsigned)__cvta_generic_to_shared(smem_dst);
    asm volatile("cp.async.cg.shared.global [%0], [%1], 16;\n"
                 :: "r"(dst), "l"(gsrc));
}

// ---------------------------------------------------------------------------
// 3xTF32 tensor-core GEMM, 128x64 tile, 8 warps (32x32 each), fused epilogue.
// mode 0: C = A.W + bias (row-major [M,N])
// mode 1: per-head RoPE * SCALE  -> g_qs  [(bh), n, d]   (BN = one head)
// mode 2: per-head RoPE + LN     -> g_lkv [(bh), n, d]
// ---------------------------------------------------------------------------
extern __shared__ float sm_gemm[];

__global__ void __launch_bounds__(256, 3) tf32gemm_kernel(
    const float* __restrict__ A, const float* __restrict__ W,
    const float* __restrict__ bias, float* __restrict__ C,
    int M, int N, int K, int mode,
    const float* __restrict__ ln_g, const float* __restrict__ ln_b)
{
    float* As = sm_gemm;                 // 2 stages of [128][KP]
    float* Bs = sm_gemm + 2 * ASTG;      // 2 stages of [32][NP2]

    int tid  = threadIdx.x;
    int wid  = tid >> 5, lane = tid & 31;
    int wm   = wid >> 1, wn = wid & 1;   // 4 x 2 warp grid
    int g    = lane >> 2, t = lane & 3;
    int row0 = blockIdx.y * BM, col0 = blockIdx.x * BN;

    float acc[2][4][4] = {};
    const int NIT = K / BKK;

    auto issue = [&](int it, int stage) {
        int k0 = it * BKK;
#pragma unroll
        for (int i = 0; i < 4; i++) {           // A: 128x32 = 1024 f4
            int cidx = tid + i * 256;
            int r = cidx >> 3, c4 = cidx & 7;
            cp16(As + stage * ASTG + r * KP + c4 * 4,
                 A + (size_t)(row0 + r) * K + k0 + c4 * 4);
        }
#pragma unroll
        for (int i = 0; i < 2; i++) {           // B: 32x64 = 512 f4
            int cidx = tid + i * 256;
            int r = cidx >> 4, c4 = cidx & 15;
            cp16(Bs + stage * BSTG + r * NP2 + c4 * 4,
                 W + (size_t)(k0 + r) * N + col0 + c4 * 4);
        }
        asm volatile("cp.async.commit_group;\n");
    };

    issue(0, 0);

    for (int it = 0; it < NIT; it++) {
        int stage = it & 1;
        if (it + 1 < NIT) {
            issue(it + 1, (it + 1) & 1);
            asm volatile("cp.async.wait_group 1;\n");
        } else {
            asm volatile("cp.async.wait_group 0;\n");
        }
        __syncthreads();

        const float* a_s = As + stage * ASTG + (wm * 32) * KP;
        const float* b_s = Bs + stage * BSTG + wn * 32;

#pragma unroll
        for (int ks = 0; ks < 4; ks++) {
            int k0 = ks * 8;
            unsigned ah[2][4], al[2][4];
            unsigned bh[4][2], bl[4][2];
#pragma unroll
            for (int mi = 0; mi < 2; mi++) {
                const float* ap  = a_s + (mi * 16 + g) * KP + k0 + t;
                const float* ap8 = ap + 8 * KP;
                split_hl(ap [0], ah[mi][0], al[mi][0]);
                split_hl(ap8[0], ah[mi][1], al[mi][1]);
                split_hl(ap [4], ah[mi][2], al[mi][2]);
                split_hl(ap8[4], ah[mi][3], al[mi][3]);
            }
#pragma unroll
            for (int ni = 0; ni < 4; ni++) {
                const float* bp = b_s + (k0 + t) * NP2 + ni * 8 + g;
                split_hl(bp[0],       bh[ni][0], bl[ni][0]);
                split_hl(bp[4 * NP2], bh[ni][1], bl[ni][1]);
            }
#pragma unroll
            for (int mi = 0; mi < 2; mi++)
#pragma unroll
                for (int ni = 0; ni < 4; ni++) {
                    mma_tf32(acc[mi][ni], al[mi], bh[ni]);
                    mma_tf32(acc[mi][ni], ah[mi], bl[ni]);
                    mma_tf32(acc[mi][ni], ah[mi], bh[ni]);
                }
        }
        __syncthreads();
    }

    if (mode == EPI_BIAS) {
#pragma unroll
        for (int mi = 0; mi < 2; mi++) {
            int r0 = row0 + wm * 32 + mi * 16 + g;
#pragma unroll
            for (int ni = 0; ni < 4; ni++) {
                int c = col0 + wn * 32 + ni * 8 + 2 * t;
                float bx = bias[c], by = bias[c + 1];
                float2 v0 = {acc[mi][ni][0] + bx, acc[mi][ni][1] + by};
                *(float2*)&C[(size_t)r0 * N + c] = v0;
                float2 v1 = {acc[mi][ni][2] + bx, acc[mi][ni][3] + by};
                *(float2*)&C[(size_t)(r0 + 8) * N + c] = v1;
            }
        }
        return;
    }

    // ---- fused RoPE(/LN) epilogue: tile = 128 tokens x one head (64 d) ----
    float* Ep = As;    // reuse A staging: 128 x EPIT = 9216 floats (exact fit)

#pragma unroll
    for (int mi = 0; mi < 2; mi++) {
        int r1 = wm * 32 + mi * 16 + g;
#pragma unroll
        for (int ni = 0; ni < 4; ni++) {
            int c = wn * 32 + ni * 8 + 2 * t;
            *(float2*)&Ep[r1 * EPIT + c] =
                make_float2(acc[mi][ni][0], acc[mi][ni][1]);
            *(float2*)&Ep[(r1 + 8) * EPIT + c] =
                make_float2(acc[mi][ni][2], acc[mi][ni][3]);
        }
    }
    __syncthreads();

    int gj = tid & 7;          // column lane within 8-thread group
    int tg = tid >> 3;         // token group 0..31

    // thread-constant rotary inv-freqs for cmod = gj + 8k (double for accuracy)
    float invd[4];
#pragma unroll
    for (int k = 0; k < 4; k++)
        invd[k] = (float)exp(-0.28782313662425575 * (double)(gj + 8 * k));

    int h  = blockIdx.x;                   // head (BN = 64 = one head)
    int b  = row0 >> 12;                   // batch (row0 multiple of 128)
    int nb = row0 & 4095;                  // token base within batch

    float lg[8], lb[8];
    if (mode == EPI_KV) {
#pragma unroll
        for (int k = 0; k < 8; k++) {
            lg[k] = ln_g[gj + 8 * k];
            lb[k] = ln_b[gj + 8 * k];
        }
    }

#pragma unroll
    for (int i = 0; i < 4; i++) {
        int tk = tg + i * 32;              // local token row
        int n  = nb + tk;                  // token position in batch

        float v[8];
#pragma unroll
        for (int k = 0; k < 8; k++) v[k] = Ep[tk * EPIT + gj + 8 * k];

        float out[8];
#pragma unroll
        for (int k = 0; k < 4; k++) {
            float arg = (float)n * invd[k];
            float sn, cs;
            sincosf(arg, &sn, &cs);
            out[k]     = v[k]     * cs - v[k + 4] * sn;   // c < 32
            out[k + 4] = v[k + 4] * cs + v[k]     * sn;   // c >= 32
        }

        size_t base = ((size_t)(b * H_ + h) * N_ + n) * D_;
        if (mode == EPI_Q) {
#pragma unroll
            for (int k = 0; k < 8; k++)
                g_qs[base + gj + 8 * k] = out[k] * SCALE_;
        } else {
            float sum = 0.f;
#pragma unroll
            for (int k = 0; k < 8; k++) sum += out[k];
            sum += __shfl_xor_sync(0xffffffffu, sum, 1);
            sum += __shfl_xor_sync(0xffffffffu, sum, 2);
            sum += __shfl_xor_sync(0xffffffffu, sum, 4);
            float mu = sum * (1.0f / 64.0f);
            float ss = 0.f;
#pragma unroll
            for (int k = 0; k < 8; k++) {
                float d = out[k] - mu;
                ss += d * d;
            }
            ss += __shfl_xor_sync(0xffffffffu, ss, 1);
            ss += __shfl_xor_sync(0xffffffffu, ss, 2);
            ss += __shfl_xor_sync(0xffffffffu, ss, 4);
            float rstd = rsqrtf(ss * (1.0f / 64.0f) + LN_EPS_);
#pragma unroll
            for (int k = 0; k < 8; k++)
                g_lkv[base + gj + 8 * k] =
                    (out[k] - mu) * rstd * lg[k] + lb[k];
        }
    }
}

// ---------------------------------------------------------------------------
// Tensorized flash attention (3xTF32 mma) — unchanged from round 8.
// ---------------------------------------------------------------------------
extern __shared__ float sm_attn[];

__global__ void __launch_bounds__(256, 3) attn_mma_kernel()
{
    float* Qs   = sm_attn;
    float* Kn   = sm_attn + 64 * PQ;
    float* Ps   = sm_attn + 128 * PQ;
    float* redm = sm_attn + 192 * PQ;
    float* reds = redm + 128;

    int bh = blockIdx.y;
    int qt = 63 - blockIdx.x;
    int q0 = qt * 64;
    bool is_lat = (q0 >= CTX_);

    int tid  = threadIdx.x;
    int wid  = tid >> 5, lane = tid & 31;
    int wm   = wid >> 1, wn = wid & 1;
    int g    = lane >> 2, t = lane & 3;

    int row0 = wm * 16 + g;
    int lrow = tid >> 4, lc4 = tid & 15;

    {
        const float4* src = (const float4*)(g_qs + ((size_t)bh * N_ + q0) * D_);
#pragma unroll
        for (int it = 0; it < 4; it++) {
            int row = lrow + it * 16;
            *(float4*)&Qs[row * PQ + lc4 * 4] = src[row * 16 + lc4];
        }
    }

    float s[4][4];
    float o[4][4] = {};
    float m0 = -3.0e38f, m1 = -3.0e38f, l0 = 0.f, l1 = 0.f;

    int ks0, ntiles;
    if (is_lat) { ks0 = 0;               ntiles = qt + 1; }
    else        { ks0 = (q0 >> 8) << 8;  ntiles = CHUNK_ / 64; }

    for (int t0 = 0; t0 < ntiles; t0++) {
        int kt0 = ks0 + t0 * 64;

        __syncthreads();

        {
            const float4* src =
                (const float4*)(g_lkv + ((size_t)bh * N_ + kt0) * D_);
#pragma unroll
            for (int it = 0; it < 4; it++) {
                int row = lrow + it * 16;
                *(float4*)&Kn[row * PQ + lc4 * 4] = src[row * 16 + lc4];
            }
        }
        __syncthreads();

#pragma unroll
        for (int ni = 0; ni < 4; ni++)
#pragma unroll
            for (int e = 0; e < 4; e++) s[ni][e] = 0.f;

#pragma unroll
        for (int ks = 0; ks < 8; ks++) {
            int k0 = ks * 8;
            unsigned ah[4], al[4], bh2[4][2], bl2[4][2];
            const float* ap  = Qs + row0 * PQ + k0 + t;
            const float* ap8 = ap + 8 * PQ;
            split_hl(ap [0], ah[0], al[0]);
            split_hl(ap8[0], ah[1], al[1]);
            split_hl(ap [4], ah[2], al[2]);
            split_hl(ap8[4], ah[3], al[3]);
#pragma unroll
            for (int ni = 0; ni < 4; ni++) {
                const float* bp = Kn + (wn * 32 + ni * 8 + g) * PQ + k0 + t;
                split_hl(bp[0], bh2[ni][0], bl2[ni][0]);
                split_hl(bp[4], bh2[ni][1], bl2[ni][1]);
            }
#pragma unroll
            for (int ni = 0; ni < 4; ni++) {
                mma_tf32(s[ni], al, bh2[ni]);
                mma_tf32(s[ni], ah, bl2[ni]);
                mma_tf32(s[ni], ah, bh2[ni]);
            }
        }

        if (is_lat && kt0 >= CTX_) {
#pragma unroll
            for (int ni = 0; ni < 4; ni++) {
                int col = wn * 32 + ni * 8 + 2 * t;
                if (kt0 + col     > q0 + row0)     s[ni][0] = -3.0e38f;
                if (kt0 + col + 1 > q0 + row0)     s[ni][1] = -3.0e38f;
                if (kt0 + col     > q0 + row0 + 8) s[ni][2] = -3.0e38f;
                if (kt0 + col + 1 > q0 + row0 + 8) s[ni][3] = -3.0e38f;
            }
        }

        float mx0 = -3.0e38f, mx1 = -3.0e38f;
#pragma unroll
        for (int ni = 0; ni < 4; ni++) {
            mx0 = fmaxf(mx0, fmaxf(s[ni][0], s[ni][1]));
            mx1 = fmaxf(mx1, fmaxf(s[ni][2], s[ni][3]));
        }
        mx0 = fmaxf(mx0, __shfl_xor_sync(0xffffffffu, mx0, 1));
        mx0 = fmaxf(mx0, __shfl_xor_sync(0xffffffffu, mx0, 2));
        mx1 = fmaxf(mx1, __shfl_xor_sync(0xffffffffu, mx1, 1));
        mx1 = fmaxf(mx1, __shfl_xor_sync(0xffffffffu, mx1, 2));
        if (t == 0) {
            redm[wn * 64 + row0]     = mx0;
            redm[wn * 64 + row0 + 8] = mx1;
        }
        __syncthreads();

        float gm0 = fmaxf(redm[row0],     redm[64 + row0]);
        float gm1 = fmaxf(redm[row0 + 8], redm[64 + row0 + 8]);
        float mn0 = fmaxf(m0, gm0), mn1 = fmaxf(m1, gm1);
        float corr0 = __expf(m0 - mn0), corr1 = __expf(m1 - mn1);
        m0 = mn0; m1 = mn1;

        float rs0 = 0.f, rs1 = 0.f;
#pragma unroll
        for (int ni = 0; ni < 4; ni++) {
            int col = wn * 32 + ni * 8 + 2 * t;
            float p0 = __expf(s[ni][0] - m0);
            float p1 = __expf(s[ni][1] - m0);
            float p2 = __expf(s[ni][2] - m1);
            float p3 = __expf(s[ni][3] - m1);
            rs0 += p0 + p1;
            rs1 += p2 + p3;
            *(float2*)&Ps[row0 * PQ + col]       = make_float2(p0, p1);
            *(float2*)&Ps[(row0 + 8) * PQ + col] = make_float2(p2, p3);
        }
        rs0 += __shfl_xor_sync(0xffffffffu, rs0, 1);
        rs0 += __shfl_xor_sync(0xffffffffu, rs0, 2);
        rs1 += __shfl_xor_sync(0xffffffffu, rs1, 1);
        rs1 += __shfl_xor_sync(0xffffffffu, rs1, 2);
        if (t == 0) {
            reds[wn * 64 + row0]     = rs0;
            reds[wn * 64 + row0 + 8] = rs1;
        }

#pragma unroll
        for (int ni = 0; ni < 4; ni++) {
            o[ni][0] *= corr0; o[ni][1] *= corr0;
            o[ni][2] *= corr1; o[ni][3] *= corr1;
        }
        __syncthreads();

        l0 = l0 * corr0 + reds[row0]     + reds[64 + row0];
        l1 = l1 * corr1 + reds[row0 + 8] + reds[64 + row0 + 8];

#pragma unroll
        for (int ks = 0; ks < 8; ks++) {
            int k0 = ks * 8;
            unsigned ah[4], al[4], bh2[4][2], bl2[4][2];
            const float* ap  = Ps + row0 * PQ + k0 + t;
            const float* ap8 = ap + 8 * PQ;
            split_hl(ap [0], ah[0], al[0]);
            split_hl(ap8[0], ah[1], al[1]);
            split_hl(ap [4], ah[2], al[2]);
            split_hl(ap8[4], ah[3], al[3]);
#pragma unroll
            for (int ni = 0; ni < 4; ni++) {
                const float* bp = Kn + (k0 + t) * PQ + wn * 32 + ni * 8 + g;
                split_hl(bp[0],      bh2[ni][0], bl2[ni][0]);
                split_hl(bp[4 * PQ], bh2[ni][1], bl2[ni][1]);
            }
#pragma unroll
            for (int ni = 0; ni < 4; ni++) {
                mma_tf32(o[ni], al, bh2[ni]);
                mma_tf32(o[ni], ah, bl2[ni]);
                mma_tf32(o[ni], ah, bh2[ni]);
            }
        }
    }

    float inv0 = 1.0f / l0, inv1 = 1.0f / l1;
    int b = bh / H_, h = bh % H_;
    int tok0 = q0 + row0;
#pragma unroll
    for (int ni = 0; ni < 4; ni++) {
        int col = h * D_ + wn * 32 + ni * 8 + 2 * t;
        float2 v0 = make_float2(o[ni][0] * inv0, o[ni][1] * inv0);
        *(float2*)&g_attn[((size_t)(b * N_ + tok0)) * DIM_ + col] = v0;
        float2 v1 = make_float2(o[ni][2] * inv1, o[ni][3] * inv1);
        *(float2*)&g_attn[((size_t)(b * N_ + tok0 + 8)) * DIM_ + col] = v1;
    }
}

// ---------------------------------------------------------------------------
// Launch
// ---------------------------------------------------------------------------
extern "C" void kernel_launch(void* const* d_in, const int* in_sizes, int n_in,
                              void* d_out, int out_size)
{
    const float* x   = (const float*)d_in[0];
    const float* Wq  = (const float*)d_in[1];
    const float* Wkv = (const float*)d_in[2];
    const float* Wo  = (const float*)d_in[3];
    const float* bo  = (const float*)d_in[4];
    const float* lng = (const float*)d_in[5];
    const float* lnb = (const float*)d_in[6];
    float* out = (float*)d_out;

    float* attn;
    cudaGetSymbolAddress((void**)&attn, g_attn);

    int attn_smem = (192 * PQ + 256) * (int)sizeof(float);   // 53,248 B
    int gemm_smem = 2 * (ASTG + BSTG) * (int)sizeof(float);  // 55,296 B

    static int attr_set = 0;
    if (!attr_set) {
        cudaFuncSetAttribute(attn_mma_kernel,
                             cudaFuncAttributeMaxDynamicSharedMemorySize,
                             attn_smem);
        cudaFuncSetAttribute(tf32gemm_kernel,
                             cudaFuncAttributeMaxDynamicSharedMemorySize,
                             gemm_smem);
        attr_set = 1;
    }

    dim3 gemm_grid(DIM_ / BN, M_ / BM);   // (16, 64)

    tf32gemm_kernel<<<gemm_grid, 256, gemm_smem>>>(
        x, Wq, nullptr, nullptr, M_, DIM_, DIM_, EPI_Q, nullptr, nullptr);
    tf32gemm_kernel<<<gemm_grid, 256, gemm_smem>>>(
        x, Wkv, nullptr, nullptr, M_, DIM_, DIM_, EPI_KV, lng, lnb);
    attn_mma_kernel<<<dim3(64, BH_), 256, attn_smem>>>();
    tf32gemm_kernel<<<gemm_grid, 256, gemm_smem>>>(
        attn, Wo, bo, out, M_, DIM_, DIM_, EPI_BIAS, nullptr, nullptr);
}